// round 5
// baseline (speedup 1.0000x reference)
#include <cuda_runtime.h>
#include <cuda_fp16.h>

#define NN   50000
#define EE   800000
#define DIN  128
#define DHID 64
#define DOUT 128

// ---------------- scratch (static device globals; no allocation) ----------------
__device__ __align__(16) float g_dinv[NN];
__device__ int   g_cnt[NN];
__device__ int   g_cur[NN];
__device__ int   g_offs[NN + 1];
__device__ int   g_csr[EE];
__device__ __align__(16) __half2 g_hs[NN * 32];      // fp16 pre-agg features (64/row)
__device__ __align__(16) float   g_agg [NN * DHID];  // gather1 result (fp32)
__device__ __align__(16) float   g_agg2[NN * DHID];  // gather2 result (fp32)

// ---------------- CSR build ----------------
__global__ void k_init(int n) {
    int i = blockIdx.x * blockDim.x + threadIdx.x;
    if (i < n) { g_cnt[i] = 0; g_cur[i] = 0; }
}

__global__ void k_count(const int* __restrict__ dst, int e) {
    int i = blockIdx.x * blockDim.x + threadIdx.x;
    if (i < e) atomicAdd(&g_cnt[dst[i]], 1);
}

// single-block scan over all n counts -> offsets + dinv
__global__ void k_scan(int n, int e) {
    __shared__ int sh[1024];
    int t = threadIdx.x;
    int ch = (n + 1023) >> 10;
    int beg = t * ch;
    int end = beg + ch; if (end > n) end = n;
    int sum = 0;
    for (int i = beg; i < end; i++) sum += g_cnt[i];
    sh[t] = sum;
    for (int off = 1; off < 1024; off <<= 1) {
        __syncthreads();
        int v = (t >= off) ? sh[t - off] : 0;
        __syncthreads();
        sh[t] += v;
    }
    __syncthreads();
    int run = sh[t] - sum;                 // exclusive prefix
    for (int i = beg; i < end; i++) {
        int c = g_cnt[i];
        g_offs[i] = run;
        g_dinv[i] = rsqrtf((float)c + 1.0f);
        run += c;
    }
    if (t == 0) g_offs[n] = e;
}

__global__ void k_fill(const int* __restrict__ src,
                       const int* __restrict__ dst, int e) {
    int i = blockIdx.x * blockDim.x + threadIdx.x;
    if (i < e) {
        int d = dst[i];
        int p = g_offs[d] + atomicAdd(&g_cur[d], 1);
        g_csr[p] = src[i];
    }
}

// ---------------- GEMM1: g_hs = fp16( (x @ W1) * dinv[row] ) ----------------
// tile 64 rows x 64 cols, 256 threads, 4x4 outputs/thread, packed f32x2 FMA over k-pairs
// xs row pitch 132 floats = 528 B: 16B-aligned rows (float4 stores) AND 8B-aligned k-pairs
__global__ void k_gemm1(const float* __restrict__ x, const float* __restrict__ W1, int n) {
    __shared__ __align__(16) float xs[64 * 132];
    __shared__ __align__(16) float Ws[DIN * DHID];   // full W1, [k][c]
    int t = threadIdx.x;
    int row0 = blockIdx.x * 64;
    int tx = t & 15;                   // cols tx*4..+3
    int ty = t >> 4;                   // rows ty*4..+3

    for (int i = t; i < DIN * DHID; i += 256) Ws[i] = W1[i];
    for (int i = t; i < 64 * 32; i += 256) {         // 64 rows x 32 float4
        int r = i >> 5, c4 = i & 31;
        int gr = row0 + r; if (gr >= n) gr = row0;
        *(float4*)&xs[r * 132 + c4 * 4] = *(const float4*)&x[gr * DIN + c4 * 4];
    }
    __syncthreads();

    unsigned long long acc[4][4];
#pragma unroll
    for (int j = 0; j < 4; j++)
#pragma unroll
        for (int c = 0; c < 4; c++) acc[j][c] = 0ull;

#pragma unroll 8
    for (int k = 0; k < DIN; k += 2) {
        float4 wk  = *(const float4*)&Ws[k * DHID + tx * 4];
        float4 wk1 = *(const float4*)&Ws[(k + 1) * DHID + tx * 4];
        unsigned long long wp[4];
        asm("mov.b64 %0, {%1,%2};" : "=l"(wp[0]) : "f"(wk.x), "f"(wk1.x));
        asm("mov.b64 %0, {%1,%2};" : "=l"(wp[1]) : "f"(wk.y), "f"(wk1.y));
        asm("mov.b64 %0, {%1,%2};" : "=l"(wp[2]) : "f"(wk.z), "f"(wk1.z));
        asm("mov.b64 %0, {%1,%2};" : "=l"(wp[3]) : "f"(wk.w), "f"(wk1.w));
#pragma unroll
        for (int j = 0; j < 4; j++) {
            unsigned long long ap = *(const unsigned long long*)&xs[(ty * 4 + j) * 132 + k];
#pragma unroll
            for (int c = 0; c < 4; c++)
                asm("fma.rn.f32x2 %0, %1, %2, %0;" : "+l"(acc[j][c]) : "l"(ap), "l"(wp[c]));
        }
    }

#pragma unroll
    for (int j = 0; j < 4; j++) {
        int gr = row0 + ty * 4 + j;
        if (gr < n) {
            float di = g_dinv[gr];
            float o[4];
#pragma unroll
            for (int c = 0; c < 4; c++) {
                float lo, hi;
                asm("mov.b64 {%0,%1}, %2;" : "=f"(lo), "=f"(hi) : "l"(acc[j][c]));
                o[c] = (lo + hi) * di;
            }
            __half2 h0 = __floats2half2_rn(o[0], o[1]);
            __half2 h1 = __floats2half2_rn(o[2], o[3]);
            g_hs[gr * 32 + tx * 2]     = h0;
            g_hs[gr * 32 + tx * 2 + 1] = h1;
        }
    }
}

// ---------------- gather: out[i] = hs[i] + sum_{s in in(i)} hs[s]  (fp16 in, fp32 acc) ----------------
__global__ void k_gather(int n, int phase) {
    int gt   = blockIdx.x * blockDim.x + threadIdx.x;
    int node = gt >> 5;
    int lane = gt & 31;
    if (node >= n) return;
    float2* __restrict__ out2 = (float2*)(phase ? g_agg2 : g_agg);

    float2 acc = __half22float2(g_hs[node * 32 + lane]);   // self-loop
    int beg = g_offs[node], end = g_offs[node + 1];
    int j = beg;
    for (; j + 4 <= end; j += 4) {
        int s0 = g_csr[j], s1 = g_csr[j + 1], s2 = g_csr[j + 2], s3 = g_csr[j + 3];
        float2 v0 = __half22float2(g_hs[s0 * 32 + lane]);
        float2 v1 = __half22float2(g_hs[s1 * 32 + lane]);
        float2 v2 = __half22float2(g_hs[s2 * 32 + lane]);
        float2 v3 = __half22float2(g_hs[s3 * 32 + lane]);
        acc.x += v0.x + v1.x + v2.x + v3.x;
        acc.y += v0.y + v1.y + v2.y + v3.y;
    }
    for (; j < end; j++) {
        int s = g_csr[j];
        float2 v = __half22float2(g_hs[s * 32 + lane]);
        acc.x += v.x; acc.y += v.y;
    }
    out2[node * 32 + lane] = acc;
}

// ---------------- relu/scale: g_hs = fp16( relu(g_agg*dinv + b1) * dinv ) ----------------
__global__ void k_relu(const float* __restrict__ b1, int n) {
    int i = blockIdx.x * blockDim.x + threadIdx.x;   // half2 index
    if (i >= n * 32) return;
    int row = i >> 5, c2 = i & 31;
    float di = g_dinv[row];
    float2 a = *(const float2*)&g_agg[row * DHID + c2 * 2];
    float2 b = *(const float2*)&b1[c2 * 2];
    float ox = fmaxf(a.x * di + b.x, 0.f) * di;
    float oy = fmaxf(a.y * di + b.y, 0.f) * di;
    g_hs[i] = __floats2half2_rn(ox, oy);
}

// ---------------- final: out = x + h1@Wl + a2@W2 + bl + b2 ----------------
// tile 32 rows x 128 cols, 256 threads, 4x4 outputs/thread, f32x2 FMA, two K=64 phases
// as row pitch 66 floats = 264 B: 8B-aligned k-pairs, scalar stores only
__global__ void k_final(const float* __restrict__ x,  const float* __restrict__ Wl,
                        const float* __restrict__ W2, const float* __restrict__ b1,
                        const float* __restrict__ bl, const float* __restrict__ b2,
                        float* __restrict__ out, int n) {
    __shared__ __align__(16) float as[32 * 66];
    __shared__ __align__(16) float Ws[DHID * DOUT];  // [k][c] 32 KB
    int t = threadIdx.x;
    int row0 = blockIdx.x * 32;
    int tx = t & 31;                   // cols tx*4..+3
    int ty = t >> 5;                   // rows ty*4..+3

    unsigned long long acc[4][4];
#pragma unroll
    for (int j = 0; j < 4; j++)
#pragma unroll
        for (int c = 0; c < 4; c++) acc[j][c] = 0ull;

    for (int phase = 0; phase < 2; phase++) {
        const float* A  = phase ? g_agg2 : g_agg;
        const float* Wg = phase ? W2 : Wl;
        __syncthreads();
        for (int i = t; i < 32 * DHID; i += 256) {
            int r = i >> 6, c = i & 63;
            int gr = row0 + r; if (gr >= n) gr = row0;
            float v = A[gr * DHID + c] * g_dinv[gr];
            if (phase == 0) v += b1[c];
            as[r * 66 + c] = v;
        }
        {
            float4* Ws4 = (float4*)Ws;
            const float4* Wg4 = (const float4*)Wg;
            for (int i = t; i < DHID * DOUT / 4; i += 256) Ws4[i] = Wg4[i];
        }
        __syncthreads();
#pragma unroll 8
        for (int k = 0; k < DHID; k += 2) {
            float4 wk  = *(const float4*)&Ws[k * DOUT + tx * 4];
            float4 wk1 = *(const float4*)&Ws[(k + 1) * DOUT + tx * 4];
            unsigned long long wp[4];
            asm("mov.b64 %0, {%1,%2};" : "=l"(wp[0]) : "f"(wk.x), "f"(wk1.x));
            asm("mov.b64 %0, {%1,%2};" : "=l"(wp[1]) : "f"(wk.y), "f"(wk1.y));
            asm("mov.b64 %0, {%1,%2};" : "=l"(wp[2]) : "f"(wk.z), "f"(wk1.z));
            asm("mov.b64 %0, {%1,%2};" : "=l"(wp[3]) : "f"(wk.w), "f"(wk1.w));
#pragma unroll
            for (int j = 0; j < 4; j++) {
                unsigned long long ap = *(const unsigned long long*)&as[(ty * 4 + j) * 66 + k];
#pragma unroll
                for (int c = 0; c < 4; c++)
                    asm("fma.rn.f32x2 %0, %1, %2, %0;" : "+l"(acc[j][c]) : "l"(ap), "l"(wp[c]));
            }
        }
    }

    float4 blv = *(const float4*)&bl[tx * 4];
    float4 b2v = *(const float4*)&b2[tx * 4];
#pragma unroll
    for (int j = 0; j < 4; j++) {
        int gr = row0 + ty * 4 + j;
        if (gr < n) {
            float4 xv = *(const float4*)&x[gr * DOUT + tx * 4];
            float o[4];
#pragma unroll
            for (int c = 0; c < 4; c++) {
                float lo, hi;
                asm("mov.b64 {%0,%1}, %2;" : "=f"(lo), "=f"(hi) : "l"(acc[j][c]));
                o[c] = lo + hi;
            }
            float4 ov;
            ov.x = o[0] + xv.x + blv.x + b2v.x;
            ov.y = o[1] + xv.y + blv.y + b2v.y;
            ov.z = o[2] + xv.z + blv.z + b2v.z;
            ov.w = o[3] + xv.w + blv.w + b2v.w;
            *(float4*)&out[gr * DOUT + tx * 4] = ov;
        }
    }
}

// ---------------- launch ----------------
extern "C" void kernel_launch(void* const* d_in, const int* in_sizes, int n_in,
                              void* d_out, int out_size) {
    const float* x  = (const float*)d_in[0];
    const int*   ei = (const int*)d_in[1];          // int32 (JAX x64 disabled)
    const float* W1 = (const float*)d_in[2];
    const float* b1 = (const float*)d_in[3];
    const float* Wl = (const float*)d_in[4];
    const float* bl = (const float*)d_in[5];
    const float* W2 = (const float*)d_in[6];
    const float* b2 = (const float*)d_in[7];
    float*       out = (float*)d_out;

    int n = in_sizes[0] / DIN;        // 50000
    int e = in_sizes[1] / 2;          // 800000
    const int* src = ei;
    const int* dst = ei + e;

    int nbN = (n + 255) / 256;
    int nbE = (e + 255) / 256;

    k_init <<<nbN, 256>>>(n);
    k_count<<<nbE, 256>>>(dst, e);
    k_scan <<<1, 1024>>>(n, e);
    k_fill <<<nbE, 256>>>(src, dst, e);

    k_gemm1 <<<(n + 63) / 64, 256>>>(x, W1, n);
    k_gather<<<(n * 32 + 255) / 256, 256>>>(n, 0);
    k_relu  <<<(n * 32 + 255) / 256, 256>>>(b1, n);
    k_gather<<<(n * 32 + 255) / 256, 256>>>(n, 1);
    k_final <<<(n + 31) / 32, 256>>>(x, Wl, W2, b1, bl, b2, out, n);
}

// round 6
// speedup vs baseline: 1.1183x; 1.1183x over previous
#include <cuda_runtime.h>
#include <cuda_fp16.h>

#define NN   50000
#define EE   800000
#define DIN  128
#define DHID 64
#define DOUT 128

// ---------------- scratch (static device globals; no allocation) ----------------
__device__ __align__(16) float g_dinv[NN];
__device__ int   g_cnt[NN];
__device__ int   g_cur[NN];
__device__ int   g_offs[NN + 1];
__device__ int   g_csr[EE];
__device__ __align__(16) __half2 g_hs[NN * 32];      // fp16 pre-agg features (64/row)
__device__ __align__(16) float   g_agg [NN * DHID];  // gather1 result (fp32)
__device__ __align__(16) float   g_agg2[NN * DHID];  // gather2 result (fp32)

// ---------------- CSR build ----------------
__global__ void k_init(int n) {
    int i = blockIdx.x * blockDim.x + threadIdx.x;
    if (i < n) { g_cnt[i] = 0; g_cur[i] = 0; }
}

__global__ void k_count(const int* __restrict__ dst, int e) {
    int i = blockIdx.x * blockDim.x + threadIdx.x;
    if (i < e) atomicAdd(&g_cnt[dst[i]], 1);
}

// single-block scan over all n counts -> offsets + dinv
__global__ void k_scan(int n, int e) {
    __shared__ int sh[1024];
    int t = threadIdx.x;
    int ch = (n + 1023) >> 10;
    int beg = t * ch;
    int end = beg + ch; if (end > n) end = n;
    int sum = 0;
    for (int i = beg; i < end; i++) sum += g_cnt[i];
    sh[t] = sum;
    for (int off = 1; off < 1024; off <<= 1) {
        __syncthreads();
        int v = (t >= off) ? sh[t - off] : 0;
        __syncthreads();
        sh[t] += v;
    }
    __syncthreads();
    int run = sh[t] - sum;                 // exclusive prefix
    for (int i = beg; i < end; i++) {
        int c = g_cnt[i];
        g_offs[i] = run;
        g_dinv[i] = rsqrtf((float)c + 1.0f);
        run += c;
    }
    if (t == 0) g_offs[n] = e;
}

__global__ void k_fill(const int* __restrict__ src,
                       const int* __restrict__ dst, int e) {
    int i = blockIdx.x * blockDim.x + threadIdx.x;
    if (i < e) {
        int d = dst[i];
        int p = g_offs[d] + atomicAdd(&g_cur[d], 1);
        g_csr[p] = src[i];
    }
}

// ---------------- GEMM1: g_hs = fp16( (x @ W1) * dinv[row] ) ----------------
// R3's proven scalar 4x4 register tile: 64 rows x 64 cols, 256 threads, K chunked by 64
__global__ void k_gemm1(const float* __restrict__ x, const float* __restrict__ W1, int n) {
    __shared__ float xs[64 * 68];     // [r][k] padded
    __shared__ float Ws[64 * 64];     // [k][c] chunk
    int t = threadIdx.x;
    int row0 = blockIdx.x * 64;
    int tx = t & 15;                  // cols tx*4..+3
    int ty = t >> 4;                  // rows ty*4..+3

    float acc[4][4];
#pragma unroll
    for (int j = 0; j < 4; j++)
#pragma unroll
        for (int c = 0; c < 4; c++) acc[j][c] = 0.f;

    for (int kc = 0; kc < DIN; kc += 64) {
        __syncthreads();
        for (int i = t; i < 64 * 64; i += 256) {
            int r = i >> 6, c = i & 63;
            int gr = row0 + r; if (gr >= n) gr = row0;
            xs[r * 68 + c] = x[gr * DIN + kc + c];
        }
        for (int i = t; i < 64 * 64; i += 256) {
            int k = i >> 6, c = i & 63;
            Ws[k * 64 + c] = W1[(kc + k) * DHID + c];
        }
        __syncthreads();
#pragma unroll 16
        for (int k = 0; k < 64; k++) {
            float4 w = *(const float4*)&Ws[k * 64 + tx * 4];
            float a0 = xs[(ty * 4 + 0) * 68 + k];
            float a1 = xs[(ty * 4 + 1) * 68 + k];
            float a2 = xs[(ty * 4 + 2) * 68 + k];
            float a3 = xs[(ty * 4 + 3) * 68 + k];
            acc[0][0] += a0 * w.x; acc[0][1] += a0 * w.y; acc[0][2] += a0 * w.z; acc[0][3] += a0 * w.w;
            acc[1][0] += a1 * w.x; acc[1][1] += a1 * w.y; acc[1][2] += a1 * w.z; acc[1][3] += a1 * w.w;
            acc[2][0] += a2 * w.x; acc[2][1] += a2 * w.y; acc[2][2] += a2 * w.z; acc[2][3] += a2 * w.w;
            acc[3][0] += a3 * w.x; acc[3][1] += a3 * w.y; acc[3][2] += a3 * w.z; acc[3][3] += a3 * w.w;
        }
    }
#pragma unroll
    for (int j = 0; j < 4; j++) {
        int gr = row0 + ty * 4 + j;
        if (gr < n) {
            float di = g_dinv[gr];
            __half2 h0 = __floats2half2_rn(acc[j][0] * di, acc[j][1] * di);
            __half2 h1 = __floats2half2_rn(acc[j][2] * di, acc[j][3] * di);
            g_hs[gr * 32 + tx * 2]     = h0;
            g_hs[gr * 32 + tx * 2 + 1] = h1;
        }
    }
}

// ---------------- gather: out[i] = hs[i] + sum_{s in in(i)} hs[s]  (fp16 in, fp32 acc) ----------------
__global__ void k_gather(int n, int phase) {
    int gt   = blockIdx.x * blockDim.x + threadIdx.x;
    int node = gt >> 5;
    int lane = gt & 31;
    if (node >= n) return;
    float2* __restrict__ out2 = (float2*)(phase ? g_agg2 : g_agg);

    float2 acc = __half22float2(g_hs[node * 32 + lane]);   // self-loop
    int beg = g_offs[node], end = g_offs[node + 1];
    int j = beg;
    for (; j + 4 <= end; j += 4) {
        int s0 = g_csr[j], s1 = g_csr[j + 1], s2 = g_csr[j + 2], s3 = g_csr[j + 3];
        float2 v0 = __half22float2(g_hs[s0 * 32 + lane]);
        float2 v1 = __half22float2(g_hs[s1 * 32 + lane]);
        float2 v2 = __half22float2(g_hs[s2 * 32 + lane]);
        float2 v3 = __half22float2(g_hs[s3 * 32 + lane]);
        acc.x += v0.x + v1.x + v2.x + v3.x;
        acc.y += v0.y + v1.y + v2.y + v3.y;
    }
    for (; j < end; j++) {
        int s = g_csr[j];
        float2 v = __half22float2(g_hs[s * 32 + lane]);
        acc.x += v.x; acc.y += v.y;
    }
    out2[node * 32 + lane] = acc;
}

// ---------------- relu/scale: g_hs = fp16( relu(g_agg*dinv + b1) * dinv ) ----------------
__global__ void k_relu(const float* __restrict__ b1, int n) {
    int i = blockIdx.x * blockDim.x + threadIdx.x;   // half2 index
    if (i >= n * 32) return;
    int row = i >> 5, c2 = i & 31;
    float di = g_dinv[row];
    float2 a = *(const float2*)&g_agg[row * DHID + c2 * 2];
    float2 b = *(const float2*)&b1[c2 * 2];
    float ox = fmaxf(a.x * di + b.x, 0.f) * di;
    float oy = fmaxf(a.y * di + b.y, 0.f) * di;
    g_hs[i] = __floats2half2_rn(ox, oy);
}

// ---------------- final: out = x + h1@Wl + a2@W2 + bl + b2 ----------------
// R3's proven scalar 4x4 tile: 32 rows x 128 cols, 256 threads, two K=64 phases
__global__ void k_final(const float* __restrict__ x,  const float* __restrict__ Wl,
                        const float* __restrict__ W2, const float* __restrict__ b1,
                        const float* __restrict__ bl, const float* __restrict__ b2,
                        float* __restrict__ out, int n) {
    __shared__ float as[32 * 64];      // [r][k]
    __shared__ float Ws[DHID * DOUT];  // [k][c] 32 KB
    int t = threadIdx.x;
    int row0 = blockIdx.x * 32;
    int tx = t & 31;                   // cols tx*4..+3
    int ty = t >> 5;                   // rows ty*4..+3

    float acc[4][4];
#pragma unroll
    for (int j = 0; j < 4; j++)
#pragma unroll
        for (int c = 0; c < 4; c++) acc[j][c] = 0.f;

    for (int phase = 0; phase < 2; phase++) {
        const float* A  = phase ? g_agg2 : g_agg;
        const float* Wg = phase ? W2 : Wl;
        __syncthreads();
        for (int i = t; i < 32 * DHID; i += 256) {
            int r = i >> 6, c = i & 63;
            int gr = row0 + r; if (gr >= n) gr = row0;
            float v = A[gr * DHID + c] * g_dinv[gr];
            if (phase == 0) v += b1[c];
            as[i] = v;
        }
        {
            float4* Ws4 = (float4*)Ws;
            const float4* Wg4 = (const float4*)Wg;
            for (int i = t; i < DHID * DOUT / 4; i += 256) Ws4[i] = Wg4[i];
        }
        __syncthreads();
#pragma unroll 16
        for (int k = 0; k < DHID; k++) {
            float4 w = *(const float4*)&Ws[k * DOUT + tx * 4];
            float a0 = as[(ty * 4 + 0) * 64 + k];
            float a1 = as[(ty * 4 + 1) * 64 + k];
            float a2 = as[(ty * 4 + 2) * 64 + k];
            float a3 = as[(ty * 4 + 3) * 64 + k];
            acc[0][0] += a0 * w.x; acc[0][1] += a0 * w.y; acc[0][2] += a0 * w.z; acc[0][3] += a0 * w.w;
            acc[1][0] += a1 * w.x; acc[1][1] += a1 * w.y; acc[1][2] += a1 * w.z; acc[1][3] += a1 * w.w;
            acc[2][0] += a2 * w.x; acc[2][1] += a2 * w.y; acc[2][2] += a2 * w.z; acc[2][3] += a2 * w.w;
            acc[3][0] += a3 * w.x; acc[3][1] += a3 * w.y; acc[3][2] += a3 * w.z; acc[3][3] += a3 * w.w;
        }
    }

    float4 blv = *(const float4*)&bl[tx * 4];
    float4 b2v = *(const float4*)&b2[tx * 4];
#pragma unroll
    for (int j = 0; j < 4; j++) {
        int gr = row0 + ty * 4 + j;
        if (gr < n) {
            float4 xv = *(const float4*)&x[gr * DOUT + tx * 4];
            float4 ov;
            ov.x = acc[j][0] + xv.x + blv.x + b2v.x;
            ov.y = acc[j][1] + xv.y + blv.y + b2v.y;
            ov.z = acc[j][2] + xv.z + blv.z + b2v.z;
            ov.w = acc[j][3] + xv.w + blv.w + b2v.w;
            *(float4*)&out[gr * DOUT + tx * 4] = ov;
        }
    }
}

// ---------------- launch ----------------
extern "C" void kernel_launch(void* const* d_in, const int* in_sizes, int n_in,
                              void* d_out, int out_size) {
    const float* x  = (const float*)d_in[0];
    const int*   ei = (const int*)d_in[1];          // int32 (JAX x64 disabled)
    const float* W1 = (const float*)d_in[2];
    const float* b1 = (const float*)d_in[3];
    const float* Wl = (const float*)d_in[4];
    const float* bl = (const float*)d_in[5];
    const float* W2 = (const float*)d_in[6];
    const float* b2 = (const float*)d_in[7];
    float*       out = (float*)d_out;

    int n = in_sizes[0] / DIN;        // 50000
    int e = in_sizes[1] / 2;          // 800000
    const int* src = ei;
    const int* dst = ei + e;

    int nbN = (n + 255) / 256;
    int nbE = (e + 255) / 256;

    k_init <<<nbN, 256>>>(n);
    k_count<<<nbE, 256>>>(dst, e);
    k_scan <<<1, 1024>>>(n, e);
    k_fill <<<nbE, 256>>>(src, dst, e);

    k_gemm1 <<<(n + 63) / 64, 256>>>(x, W1, n);
    k_gather<<<(n * 32 + 255) / 256, 256>>>(n, 0);
    k_relu  <<<(n * 32 + 255) / 256, 256>>>(b1, n);
    k_gather<<<(n * 32 + 255) / 256, 256>>>(n, 1);
    k_final <<<(n + 31) / 32, 256>>>(x, Wl, W2, b1, bl, b2, out, n);
}

// round 8
// speedup vs baseline: 1.2864x; 1.1503x over previous
#include <cuda_runtime.h>
#include <cuda_fp16.h>

#define NN   50000
#define EE   800000
#define DIN  128
#define DHID 64
#define DOUT 128

// ---------------- scratch (static device globals; no allocation) ----------------
__device__ __align__(16) float g_dinv[NN];
__device__ int   g_cnt[NN];
__device__ int   g_cur[NN];
__device__ int   g_offs[NN + 1];
__device__ int   g_csr[EE];
__device__ __align__(16) __half2 g_hs[NN * 32];      // fp16 pre-agg features (64/row)
__device__ __align__(16) float   g_agg [NN * DHID];  // gather1 result (fp32)
__device__ __align__(16) float   g_agg2[NN * DHID];  // gather2 result (fp32)

// ---------------- CSR build ----------------
__global__ void k_init(int n) {
    int i = blockIdx.x * blockDim.x + threadIdx.x;
    if (i < n) { g_cnt[i] = 0; g_cur[i] = 0; }
}

__global__ void k_count(const int* __restrict__ dst, int e) {
    int i = blockIdx.x * blockDim.x + threadIdx.x;
    if (i < e) atomicAdd(&g_cnt[dst[i]], 1);
}

// single-block scan over all n counts -> offsets ONLY (no MUFU here!)
__global__ void k_scan(int n, int e) {
    __shared__ int sh[1024];
    int t = threadIdx.x;
    int ch = (n + 1023) >> 10;
    int beg = t * ch;
    int end = beg + ch; if (end > n) end = n;
    int sum = 0;
    for (int i = beg; i < end; i++) sum += g_cnt[i];
    sh[t] = sum;
    for (int off = 1; off < 1024; off <<= 1) {
        __syncthreads();
        int v = (t >= off) ? sh[t - off] : 0;
        __syncthreads();
        sh[t] += v;
    }
    __syncthreads();
    int run = sh[t] - sum;                 // exclusive prefix
    for (int i = beg; i < end; i++) {
        g_offs[i] = run;
        run += g_cnt[i];
    }
    if (t == 0) g_offs[n] = e;
}

// parallel dinv: rsqrt spread over the whole chip (MUFU rt=8/SMSP serializes on 1 block!)
__global__ void k_dinv(int n) {
    int i = blockIdx.x * blockDim.x + threadIdx.x;
    if (i < n) g_dinv[i] = rsqrtf((float)g_cnt[i] + 1.0f);
}

__global__ void k_fill(const int* __restrict__ src,
                       const int* __restrict__ dst, int e) {
    int i = blockIdx.x * blockDim.x + threadIdx.x;
    if (i < e) {
        int d = dst[i];
        int p = g_offs[d] + atomicAdd(&g_cur[d], 1);
        g_csr[p] = src[i];
    }
}

// ---------------- GEMM1: g_hs = fp16( (x @ W1) * dinv[row] ) ----------------
// scalar 4x4 register tile: 64 rows x 64 cols, 256 threads, K chunked by 64
__global__ void k_gemm1(const float* __restrict__ x, const float* __restrict__ W1, int n) {
    __shared__ float xs[64 * 68];     // [r][k] padded
    __shared__ float Ws[64 * 64];     // [k][c] chunk
    int t = threadIdx.x;
    int row0 = blockIdx.x * 64;
    int tx = t & 15;                  // cols tx*4..+3
    int ty = t >> 4;                  // rows ty*4..+3

    float acc[4][4];
#pragma unroll
    for (int j = 0; j < 4; j++)
#pragma unroll
        for (int c = 0; c < 4; c++) acc[j][c] = 0.f;

    for (int kc = 0; kc < DIN; kc += 64) {
        __syncthreads();
        for (int i = t; i < 64 * 64; i += 256) {
            int r = i >> 6, c = i & 63;
            int gr = row0 + r; if (gr >= n) gr = row0;
            xs[r * 68 + c] = x[gr * DIN + kc + c];
        }
        for (int i = t; i < 64 * 64; i += 256) {
            int k = i >> 6, c = i & 63;
            Ws[k * 64 + c] = W1[(kc + k) * DHID + c];
        }
        __syncthreads();
#pragma unroll 16
        for (int k = 0; k < 64; k++) {
            float4 w = *(const float4*)&Ws[k * 64 + tx * 4];
            float a0 = xs[(ty * 4 + 0) * 68 + k];
            float a1 = xs[(ty * 4 + 1) * 68 + k];
            float a2 = xs[(ty * 4 + 2) * 68 + k];
            float a3 = xs[(ty * 4 + 3) * 68 + k];
            acc[0][0] += a0 * w.x; acc[0][1] += a0 * w.y; acc[0][2] += a0 * w.z; acc[0][3] += a0 * w.w;
            acc[1][0] += a1 * w.x; acc[1][1] += a1 * w.y; acc[1][2] += a1 * w.z; acc[1][3] += a1 * w.w;
            acc[2][0] += a2 * w.x; acc[2][1] += a2 * w.y; acc[2][2] += a2 * w.z; acc[2][3] += a2 * w.w;
            acc[3][0] += a3 * w.x; acc[3][1] += a3 * w.y; acc[3][2] += a3 * w.z; acc[3][3] += a3 * w.w;
        }
    }
#pragma unroll
    for (int j = 0; j < 4; j++) {
        int gr = row0 + ty * 4 + j;
        if (gr < n) {
            float di = g_dinv[gr];
            __half2 h0 = __floats2half2_rn(acc[j][0] * di, acc[j][1] * di);
            __half2 h1 = __floats2half2_rn(acc[j][2] * di, acc[j][3] * di);
            g_hs[gr * 32 + tx * 2]     = h0;
            g_hs[gr * 32 + tx * 2 + 1] = h1;
        }
    }
}

// ---------------- gather: out[i] = hs[i] + sum_{s in in(i)} hs[s]  (fp16 in, fp32 acc) ----------------
__global__ void k_gather(int n, int phase) {
    int gt   = blockIdx.x * blockDim.x + threadIdx.x;
    int node = gt >> 5;
    int lane = gt & 31;
    if (node >= n) return;
    float2* __restrict__ out2 = (float2*)(phase ? g_agg2 : g_agg);

    float2 acc = __half22float2(g_hs[node * 32 + lane]);   // self-loop
    int beg = g_offs[node], end = g_offs[node + 1];
    int j = beg;
    for (; j + 4 <= end; j += 4) {
        int s0 = g_csr[j], s1 = g_csr[j + 1], s2 = g_csr[j + 2], s3 = g_csr[j + 3];
        float2 v0 = __half22float2(g_hs[s0 * 32 + lane]);
        float2 v1 = __half22float2(g_hs[s1 * 32 + lane]);
        float2 v2 = __half22float2(g_hs[s2 * 32 + lane]);
        float2 v3 = __half22float2(g_hs[s3 * 32 + lane]);
        acc.x += v0.x + v1.x + v2.x + v3.x;
        acc.y += v0.y + v1.y + v2.y + v3.y;
    }
    for (; j < end; j++) {
        int s = g_csr[j];
        float2 v = __half22float2(g_hs[s * 32 + lane]);
        acc.x += v.x; acc.y += v.y;
    }
    out2[node * 32 + lane] = acc;
}

// ---------------- relu/scale: g_hs = fp16( relu(g_agg*dinv + b1) * dinv ) ----------------
__global__ void k_relu(const float* __restrict__ b1, int n) {
    int i = blockIdx.x * blockDim.x + threadIdx.x;   // half2 index
    if (i >= n * 32) return;
    int row = i >> 5, c2 = i & 31;
    float di = g_dinv[row];
    float2 a = *(const float2*)&g_agg[row * DHID + c2 * 2];
    float2 b = *(const float2*)&b1[c2 * 2];
    float ox = fmaxf(a.x * di + b.x, 0.f) * di;
    float oy = fmaxf(a.y * di + b.y, 0.f) * di;
    g_hs[i] = __floats2half2_rn(ox, oy);
}

// ---------------- final: out = x + h1@Wl + a2@W2 + bl + b2 ----------------
// scalar 4x4 tile: 32 rows x 128 cols, 256 threads, two K=64 phases
__global__ void k_final(const float* __restrict__ x,  const float* __restrict__ Wl,
                        const float* __restrict__ W2, const float* __restrict__ b1,
                        const float* __restrict__ bl, const float* __restrict__ b2,
                        float* __restrict__ out, int n) {
    __shared__ float as[32 * 64];      // [r][k]
    __shared__ float Ws[DHID * DOUT];  // [k][c] 32 KB
    int t = threadIdx.x;
    int row0 = blockIdx.x * 32;
    int tx = t & 31;                   // cols tx*4..+3
    int ty = t >> 5;                   // rows ty*4..+3

    float acc[4][4];
#pragma unroll
    for (int j = 0; j < 4; j++)
#pragma unroll
        for (int c = 0; c < 4; c++) acc[j][c] = 0.f;

    for (int phase = 0; phase < 2; phase++) {
        const float* A  = phase ? g_agg2 : g_agg;
        const float* Wg = phase ? W2 : Wl;
        __syncthreads();
        for (int i = t; i < 32 * DHID; i += 256) {
            int r = i >> 6, c = i & 63;
            int gr = row0 + r; if (gr >= n) gr = row0;
            float v = A[gr * DHID + c] * g_dinv[gr];
            if (phase == 0) v += b1[c];
            as[i] = v;
        }
        {
            float4* Ws4 = (float4*)Ws;
            const float4* Wg4 = (const float4*)Wg;
            for (int i = t; i < DHID * DOUT / 4; i += 256) Ws4[i] = Wg4[i];
        }
        __syncthreads();
#pragma unroll 16
        for (int k = 0; k < DHID; k++) {
            float4 w = *(const float4*)&Ws[k * DOUT + tx * 4];
            float a0 = as[(ty * 4 + 0) * 64 + k];
            float a1 = as[(ty * 4 + 1) * 64 + k];
            float a2 = as[(ty * 4 + 2) * 64 + k];
            float a3 = as[(ty * 4 + 3) * 64 + k];
            acc[0][0] += a0 * w.x; acc[0][1] += a0 * w.y; acc[0][2] += a0 * w.z; acc[0][3] += a0 * w.w;
            acc[1][0] += a1 * w.x; acc[1][1] += a1 * w.y; acc[1][2] += a1 * w.z; acc[1][3] += a1 * w.w;
            acc[2][0] += a2 * w.x; acc[2][1] += a2 * w.y; acc[2][2] += a2 * w.z; acc[2][3] += a2 * w.w;
            acc[3][0] += a3 * w.x; acc[3][1] += a3 * w.y; acc[3][2] += a3 * w.z; acc[3][3] += a3 * w.w;
        }
    }

    float4 blv = *(const float4*)&bl[tx * 4];
    float4 b2v = *(const float4*)&b2[tx * 4];
#pragma unroll
    for (int j = 0; j < 4; j++) {
        int gr = row0 + ty * 4 + j;
        if (gr < n) {
            float4 xv = *(const float4*)&x[gr * DOUT + tx * 4];
            float4 ov;
            ov.x = acc[j][0] + xv.x + blv.x + b2v.x;
            ov.y = acc[j][1] + xv.y + blv.y + b2v.y;
            ov.z = acc[j][2] + xv.z + blv.z + b2v.z;
            ov.w = acc[j][3] + xv.w + blv.w + b2v.w;
            *(float4*)&out[gr * DOUT + tx * 4] = ov;
        }
    }
}

// ---------------- launch ----------------
extern "C" void kernel_launch(void* const* d_in, const int* in_sizes, int n_in,
                              void* d_out, int out_size) {
    const float* x  = (const float*)d_in[0];
    const int*   ei = (const int*)d_in[1];          // int32 (JAX x64 disabled)
    const float* W1 = (const float*)d_in[2];
    const float* b1 = (const float*)d_in[3];
    const float* Wl = (const float*)d_in[4];
    const float* bl = (const float*)d_in[5];
    const float* W2 = (const float*)d_in[6];
    const float* b2 = (const float*)d_in[7];
    float*       out = (float*)d_out;

    int n = in_sizes[0] / DIN;        // 50000
    int e = in_sizes[1] / 2;          // 800000
    const int* src = ei;
    const int* dst = ei + e;

    int nbN = (n + 255) / 256;
    int nbE = (e + 255) / 256;

    k_init <<<nbN, 256>>>(n);
    k_count<<<nbE, 256>>>(dst, e);
    k_scan <<<1, 1024>>>(n, e);
    k_dinv <<<nbN, 256>>>(n);
    k_fill <<<nbE, 256>>>(src, dst, e);

    k_gemm1 <<<(n + 63) / 64, 256>>>(x, W1, n);
    k_gather<<<(n * 32 + 255) / 256, 256>>>(n, 0);
    k_relu  <<<(n * 32 + 255) / 256, 256>>>(b1, n);
    k_gather<<<(n * 32 + 255) / 256, 256>>>(n, 1);
    k_final <<<(n + 31) / 32, 256>>>(x, Wl, W2, b1, bl, b2, out, n);
}

// round 9
// speedup vs baseline: 1.3197x; 1.0259x over previous
#include <cuda_runtime.h>
#include <cuda_fp16.h>

#define NN   50000
#define EE   800000
#define DIN  128
#define DHID 64
#define DOUT 128

// ---------------- scratch (static device globals; no allocation) ----------------
__device__ __align__(16) float g_dinv[NN];
__device__ int   g_cnt[NN];      // zero at load; re-zeroed by k_gemm1 each call
__device__ int   g_cur[NN];      // zero at load; re-zeroed by k_gemm1 each call (before k_fill)
__device__ int   g_offs[NN + 1];
__device__ int   g_csr[EE];
__device__ __align__(16) __half2 g_hs[NN * 32];      // fp16 pre-agg features (64/row)
__device__ __align__(16) float   g_agg [NN * DHID];  // gather1 result (fp32, = conv1 pre-norm)
__device__ __align__(16) float   g_agg2[NN * DHID];  // gather2 result (fp32)

// ---------------- CSR build ----------------
__global__ void k_count(const int* __restrict__ dst, int e) {
    int i = blockIdx.x * blockDim.x + threadIdx.x;
    if (i < e) atomicAdd(&g_cnt[dst[i]], 1);
}

// single-block scan over all n counts -> offsets ONLY (no MUFU, no extra work)
__global__ void k_scan(int n, int e) {
    __shared__ int sh[1024];
    int t = threadIdx.x;
    int ch = (n + 1023) >> 10;
    int beg = t * ch;
    int end = beg + ch; if (end > n) end = n;
    int sum = 0;
    for (int i = beg; i < end; i++) sum += g_cnt[i];
    sh[t] = sum;
    for (int off = 1; off < 1024; off <<= 1) {
        __syncthreads();
        int v = (t >= off) ? sh[t - off] : 0;
        __syncthreads();
        sh[t] += v;
    }
    __syncthreads();
    int run = sh[t] - sum;                 // exclusive prefix
    for (int i = beg; i < end; i++) {
        g_offs[i] = run;
        run += g_cnt[i];
    }
    if (t == 0) g_offs[n] = e;
}

// parallel dinv (spread over the chip)
__global__ void k_dinv(int n) {
    int i = blockIdx.x * blockDim.x + threadIdx.x;
    if (i < n) g_dinv[i] = rsqrtf((float)g_cnt[i] + 1.0f);
}

__global__ void k_fill(const int* __restrict__ src,
                       const int* __restrict__ dst, int e) {
    int i = blockIdx.x * blockDim.x + threadIdx.x;
    if (i < e) {
        int d = dst[i];
        int p = g_offs[d] + atomicAdd(&g_cur[d], 1);
        g_csr[p] = src[i];
    }
}

// ---------------- GEMM1: g_hs = fp16( (x @ W1) * dinv[row] ) ----------------
// Also re-zeroes g_cnt/g_cur: g_cnt no longer needed (dinv done), g_cur must be 0 before k_fill.
// scalar 4x4 register tile: 64 rows x 64 cols, 256 threads, K chunked by 64
__global__ void k_gemm1(const float* __restrict__ x, const float* __restrict__ W1, int n) {
    __shared__ float xs[64 * 68];     // [r][k] padded
    __shared__ float Ws[64 * 64];     // [k][c] chunk
    int t = threadIdx.x;
    int row0 = blockIdx.x * 64;

    // counter reset for this call's k_fill and the next replay's k_count
    for (int i = blockIdx.x * 256 + t; i < n; i += gridDim.x * 256) {
        g_cnt[i] = 0; g_cur[i] = 0;
    }

    int tx = t & 15;                  // cols tx*4..+3
    int ty = t >> 4;                  // rows ty*4..+3

    float acc[4][4];
#pragma unroll
    for (int j = 0; j < 4; j++)
#pragma unroll
        for (int c = 0; c < 4; c++) acc[j][c] = 0.f;

    for (int kc = 0; kc < DIN; kc += 64) {
        __syncthreads();
        for (int i = t; i < 64 * 64; i += 256) {
            int r = i >> 6, c = i & 63;
            int gr = row0 + r; if (gr >= n) gr = row0;
            xs[r * 68 + c] = x[gr * DIN + kc + c];
        }
        for (int i = t; i < 64 * 64; i += 256) {
            int k = i >> 6, c = i & 63;
            Ws[k * 64 + c] = W1[(kc + k) * DHID + c];
        }
        __syncthreads();
#pragma unroll 16
        for (int k = 0; k < 64; k++) {
            float4 w = *(const float4*)&Ws[k * 64 + tx * 4];
            float a0 = xs[(ty * 4 + 0) * 68 + k];
            float a1 = xs[(ty * 4 + 1) * 68 + k];
            float a2 = xs[(ty * 4 + 2) * 68 + k];
            float a3 = xs[(ty * 4 + 3) * 68 + k];
            acc[0][0] += a0 * w.x; acc[0][1] += a0 * w.y; acc[0][2] += a0 * w.z; acc[0][3] += a0 * w.w;
            acc[1][0] += a1 * w.x; acc[1][1] += a1 * w.y; acc[1][2] += a1 * w.z; acc[1][3] += a1 * w.w;
            acc[2][0] += a2 * w.x; acc[2][1] += a2 * w.y; acc[2][2] += a2 * w.z; acc[2][3] += a2 * w.w;
            acc[3][0] += a3 * w.x; acc[3][1] += a3 * w.y; acc[3][2] += a3 * w.z; acc[3][3] += a3 * w.w;
        }
    }
#pragma unroll
    for (int j = 0; j < 4; j++) {
        int gr = row0 + ty * 4 + j;
        if (gr < n) {
            float di = g_dinv[gr];
            __half2 h0 = __floats2half2_rn(acc[j][0] * di, acc[j][1] * di);
            __half2 h1 = __floats2half2_rn(acc[j][2] * di, acc[j][3] * di);
            g_hs[gr * 32 + tx * 2]     = h0;
            g_hs[gr * 32 + tx * 2 + 1] = h1;
        }
    }
}

// ---------------- gather1: agg = self + neighbors; then fused relu epilogue ----------------
// g_agg[i]  = hs[i] + sum hs[s]                     (fp32, needed by k_final phase 0)
// g_hs[i]   = fp16( relu(agg*dinv + b1) * dinv )     (input to gather2)
__global__ void k_gather1(const float* __restrict__ b1, int n) {
    int gt   = blockIdx.x * blockDim.x + threadIdx.x;
    int node = gt >> 5;
    int lane = gt & 31;
    if (node >= n) return;

    float2 acc = __half22float2(g_hs[node * 32 + lane]);   // self-loop
    int beg = g_offs[node], end = g_offs[node + 1];
    int j = beg;
    for (; j + 4 <= end; j += 4) {
        int s0 = g_csr[j], s1 = g_csr[j + 1], s2 = g_csr[j + 2], s3 = g_csr[j + 3];
        float2 v0 = __half22float2(g_hs[s0 * 32 + lane]);
        float2 v1 = __half22float2(g_hs[s1 * 32 + lane]);
        float2 v2 = __half22float2(g_hs[s2 * 32 + lane]);
        float2 v3 = __half22float2(g_hs[s3 * 32 + lane]);
        acc.x += v0.x + v1.x + v2.x + v3.x;
        acc.y += v0.y + v1.y + v2.y + v3.y;
    }
    for (; j < end; j++) {
        int s = g_csr[j];
        float2 v = __half22float2(g_hs[s * 32 + lane]);
        acc.x += v.x; acc.y += v.y;
    }
    ((float2*)g_agg)[node * 32 + lane] = acc;

    // fused relu/scale epilogue (writes AFTER all reads of g_hs? No: other warps may still
    // read old g_hs rows for THIS phase — but every consumer of row `node` reads the row
    // written by k_gemm1; we overwrite row `node` only here. Hazard: another block may later
    // read g_hs[node] as a neighbor. So we must NOT overwrite g_hs in this kernel!
    // -> write to a staging half of g_hs? Instead store relu'd result into g_hs2 region:
    //    we reuse g_agg2 as fp16 staging is messy; use dedicated buffer below.
    float di = g_dinv[node];
    float2 b = *(const float2*)&b1[lane * 2];
    float ox = fmaxf(acc.x * di + b.x, 0.f) * di;
    float oy = fmaxf(acc.y * di + b.y, 0.f) * di;
    ((__half2*)g_agg2)[node * 32 + lane] = __floats2half2_rn(ox, oy);  // stage in g_agg2 (fp16 region)
}

// ---------------- gather2: reads staged fp16 (in g_agg2's first half), writes g_agg2f ----------------
__device__ __align__(16) float g_agg2f[NN * DHID];   // gather2 result (fp32)

__global__ void k_gather2(int n) {
    int gt   = blockIdx.x * blockDim.x + threadIdx.x;
    int node = gt >> 5;
    int lane = gt & 31;
    if (node >= n) return;
    const __half2* __restrict__ hs = (const __half2*)g_agg2;

    float2 acc = __half22float2(hs[node * 32 + lane]);   // self-loop
    int beg = g_offs[node], end = g_offs[node + 1];
    int j = beg;
    for (; j + 4 <= end; j += 4) {
        int s0 = g_csr[j], s1 = g_csr[j + 1], s2 = g_csr[j + 2], s3 = g_csr[j + 3];
        float2 v0 = __half22float2(hs[s0 * 32 + lane]);
        float2 v1 = __half22float2(hs[s1 * 32 + lane]);
        float2 v2 = __half22float2(hs[s2 * 32 + lane]);
        float2 v3 = __half22float2(hs[s3 * 32 + lane]);
        acc.x += v0.x + v1.x + v2.x + v3.x;
        acc.y += v0.y + v1.y + v2.y + v3.y;
    }
    for (; j < end; j++) {
        int s = g_csr[j];
        float2 v = __half22float2(hs[s * 32 + lane]);
        acc.x += v.x; acc.y += v.y;
    }
    ((float2*)g_agg2f)[node * 32 + lane] = acc;
}

// ---------------- final: out = x + h1@Wl + a2@W2 + bl + b2 ----------------
// h1 = g_agg*dinv + b1 (phase 0, Wl);  a2 = g_agg2f*dinv (phase 1, W2)
__global__ void k_final(const float* __restrict__ x,  const float* __restrict__ Wl,
                        const float* __restrict__ W2, const float* __restrict__ b1,
                        const float* __restrict__ bl, const float* __restrict__ b2,
                        float* __restrict__ out, int n) {
    __shared__ float as[32 * 64];      // [r][k]
    __shared__ float Ws[DHID * DOUT];  // [k][c] 32 KB
    int t = threadIdx.x;
    int row0 = blockIdx.x * 32;
    int tx = t & 31;                   // cols tx*4..+3
    int ty = t >> 5;                   // rows ty*4..+3

    float acc[4][4];
#pragma unroll
    for (int j = 0; j < 4; j++)
#pragma unroll
        for (int c = 0; c < 4; c++) acc[j][c] = 0.f;

    for (int phase = 0; phase < 2; phase++) {
        const float* A  = phase ? g_agg2f : g_agg;
        const float* Wg = phase ? W2 : Wl;
        __syncthreads();
        for (int i = t; i < 32 * DHID; i += 256) {
            int r = i >> 6, c = i & 63;
            int gr = row0 + r; if (gr >= n) gr = row0;
            float v = A[gr * DHID + c] * g_dinv[gr];
            if (phase == 0) v += b1[c];
            as[i] = v;
        }
        {
            float4* Ws4 = (float4*)Ws;
            const float4* Wg4 = (const float4*)Wg;
            for (int i = t; i < DHID * DOUT / 4; i += 256) Ws4[i] = Wg4[i];
        }
        __syncthreads();
#pragma unroll 16
        for (int k = 0; k < DHID; k++) {
            float4 w = *(const float4*)&Ws[k * DOUT + tx * 4];
            float a0 = as[(ty * 4 + 0) * 64 + k];
            float a1 = as[(ty * 4 + 1) * 64 + k];
            float a2 = as[(ty * 4 + 2) * 64 + k];
            float a3 = as[(ty * 4 + 3) * 64 + k];
            acc[0][0] += a0 * w.x; acc[0][1] += a0 * w.y; acc[0][2] += a0 * w.z; acc[0][3] += a0 * w.w;
            acc[1][0] += a1 * w.x; acc[1][1] += a1 * w.y; acc[1][2] += a1 * w.z; acc[1][3] += a1 * w.w;
            acc[2][0] += a2 * w.x; acc[2][1] += a2 * w.y; acc[2][2] += a2 * w.z; acc[2][3] += a2 * w.w;
            acc[3][0] += a3 * w.x; acc[3][1] += a3 * w.y; acc[3][2] += a3 * w.z; acc[3][3] += a3 * w.w;
        }
    }

    float4 blv = *(const float4*)&bl[tx * 4];
    float4 b2v = *(const float4*)&b2[tx * 4];
#pragma unroll
    for (int j = 0; j < 4; j++) {
        int gr = row0 + ty * 4 + j;
        if (gr < n) {
            float4 xv = *(const float4*)&x[gr * DOUT + tx * 4];
            float4 ov;
            ov.x = acc[j][0] + xv.x + blv.x + b2v.x;
            ov.y = acc[j][1] + xv.y + blv.y + b2v.y;
            ov.z = acc[j][2] + xv.z + blv.z + b2v.z;
            ov.w = acc[j][3] + xv.w + blv.w + b2v.w;
            *(float4*)&out[gr * DOUT + tx * 4] = ov;
        }
    }
}

// ---------------- launch ----------------
// Order chosen so the ncu-captured slot (launch index 3) = k_gemm1.
extern "C" void kernel_launch(void* const* d_in, const int* in_sizes, int n_in,
                              void* d_out, int out_size) {
    const float* x  = (const float*)d_in[0];
    const int*   ei = (const int*)d_in[1];          // int32 (JAX x64 disabled)
    const float* W1 = (const float*)d_in[2];
    const float* b1 = (const float*)d_in[3];
    const float* Wl = (const float*)d_in[4];
    const float* bl = (const float*)d_in[5];
    const float* W2 = (const float*)d_in[6];
    const float* b2 = (const float*)d_in[7];
    float*       out = (float*)d_out;

    int n = in_sizes[0] / DIN;        // 50000
    int e = in_sizes[1] / 2;          // 800000
    const int* src = ei;
    const int* dst = ei + e;

    int nbN = (n + 255) / 256;
    int nbE = (e + 255) / 256;

    k_count  <<<nbE, 256>>>(dst, e);                       // 0
    k_scan   <<<1, 1024>>>(n, e);                          // 1
    k_dinv   <<<nbN, 256>>>(n);                            // 2
    k_gemm1  <<<(n + 63) / 64, 256>>>(x, W1, n);           // 3  <- profiled slot
    k_fill   <<<nbE, 256>>>(src, dst, e);                  // 4
    k_gather1<<<(n * 32 + 255) / 256, 256>>>(b1, n);       // 5  (+fused relu)
    k_gather2<<<(n * 32 + 255) / 256, 256>>>(n);           // 6
    k_final  <<<(n + 31) / 32, 256>>>(x, Wl, W2, b1, bl, b2, out, n);  // 7
}

// round 10
// speedup vs baseline: 1.7342x; 1.3141x over previous
#include <cuda_runtime.h>
#include <cuda_fp16.h>

#define NN   50000
#define EE   800000
#define DIN  128
#define DHID 64
#define DOUT 128

// ---------------- scratch (static device globals; no allocation) ----------------
__device__ __align__(16) float g_dinv[NN];
__device__ int   g_cnt[NN];      // zero at load; re-zeroed by k_gemm1 each call
__device__ int   g_cur[NN];      // zero at load; re-zeroed by k_gemm1 (before k_fill)
__device__ int   g_offs[NN + 1];
__device__ int   g_csr[EE];
__device__ int   g_part[256];
__device__ int   g_part2[256];
__device__ __align__(16) __half2 g_hs[NN * 32];      // fp16 conv1 pre-agg features
__device__ __align__(16) __half2 g_zs[NN * 32];      // fp16 conv2 pre-agg features (staged by gather1)
__device__ __align__(16) float   g_agg [NN * DHID];  // gather1 result (fp32)
__device__ __align__(16) float   g_agg2[NN * DHID];  // gather2 result (fp32)

// ---------------- CSR build ----------------
__global__ void k_count(const int* __restrict__ dst, int e) {
    int i = blockIdx.x * blockDim.x + threadIdx.x;
    if (i < e) atomicAdd(&g_cnt[dst[i]], 1);
}

// parallel 3-stage scan (proven in the 147.6us build)
__global__ void k_scan1(int n) {
    __shared__ int sh[256];
    int t = threadIdx.x;
    int i = blockIdx.x * 256 + t;
    int v = (i < n) ? g_cnt[i] : 0;
    sh[t] = v;
    for (int off = 1; off < 256; off <<= 1) {
        __syncthreads();
        int x = (t >= off) ? sh[t - off] : 0;
        __syncthreads();
        sh[t] += x;
    }
    __syncthreads();
    if (i < n) g_offs[i] = sh[t] - v;          // block-local exclusive
    if (t == 255) g_part[blockIdx.x] = sh[255];
}

__global__ void k_scan2(int nb) {
    __shared__ int sh[256];
    int t = threadIdx.x;
    int v = (t < nb) ? g_part[t] : 0;
    sh[t] = v;
    for (int off = 1; off < 256; off <<= 1) {
        __syncthreads();
        int x = (t >= off) ? sh[t - off] : 0;
        __syncthreads();
        sh[t] += x;
    }
    __syncthreads();
    g_part2[t] = sh[t] - v;
}

__global__ void k_scan3(int n, int e) {
    int i = blockIdx.x * 256 + threadIdx.x;
    if (i < n) {
        g_offs[i] += g_part2[blockIdx.x];
        g_dinv[i]  = rsqrtf((float)g_cnt[i] + 1.0f);
    }
    if (i == 0) g_offs[n] = e;
}

__global__ void k_fill(const int* __restrict__ src,
                       const int* __restrict__ dst, int e) {
    int i = blockIdx.x * blockDim.x + threadIdx.x;
    if (i < e) {
        int d = dst[i];
        int p = g_offs[d] + atomicAdd(&g_cur[d], 1);
        g_csr[p] = src[i];
    }
}

// ---------------- GEMM1: g_hs = fp16( (x @ W1) * dinv[row] ) ----------------
// 64x64 tile, 256 threads, 4x4 out/thread; K blocked by 64, k-stepped by 4 with all-float4 LDS.
// Also re-zeroes g_cnt/g_cur for this call's k_fill and the next replay's k_count.
__global__ void k_gemm1(const float* __restrict__ x, const float* __restrict__ W1, int n) {
    __shared__ __align__(16) float xs[64 * 68];   // [r][k], pitch 272 B (16B-aligned)
    __shared__ __align__(16) float Ws[64 * 64];   // [k][c] chunk
    int t = threadIdx.x;
    int row0 = blockIdx.x * 64;

    for (int i = blockIdx.x * 256 + t; i < n; i += gridDim.x * 256) {
        g_cnt[i] = 0; g_cur[i] = 0;
    }

    int tx = t & 15;                  // cols tx*4..+3
    int ty = t >> 4;                  // rows ty*4..+3

    float acc[4][4];
#pragma unroll
    for (int j = 0; j < 4; j++)
#pragma unroll
        for (int c = 0; c < 4; c++) acc[j][c] = 0.f;

    for (int kc = 0; kc < DIN; kc += 64) {
        __syncthreads();
        for (int i = t; i < 64 * 16; i += 256) {       // 64 rows x 16 float4
            int r = i >> 4, c4 = i & 15;
            int gr = row0 + r; if (gr >= n) gr = row0;
            *(float4*)&xs[r * 68 + c4 * 4] = *(const float4*)&x[gr * DIN + kc + c4 * 4];
        }
        for (int i = t; i < 64 * 16; i += 256) {       // 64 k x 16 float4
            int k = i >> 4, c4 = i & 15;
            *(float4*)&Ws[k * 64 + c4 * 4] = *(const float4*)&W1[(kc + k) * DHID + c4 * 4];
        }
        __syncthreads();
#pragma unroll
        for (int k = 0; k < 64; k += 4) {
            float4 a0 = *(const float4*)&xs[(ty * 4 + 0) * 68 + k];
            float4 a1 = *(const float4*)&xs[(ty * 4 + 1) * 68 + k];
            float4 a2 = *(const float4*)&xs[(ty * 4 + 2) * 68 + k];
            float4 a3 = *(const float4*)&xs[(ty * 4 + 3) * 68 + k];
            float4 w0 = *(const float4*)&Ws[(k + 0) * 64 + tx * 4];
            float4 w1 = *(const float4*)&Ws[(k + 1) * 64 + tx * 4];
            float4 w2 = *(const float4*)&Ws[(k + 2) * 64 + tx * 4];
            float4 w3 = *(const float4*)&Ws[(k + 3) * 64 + tx * 4];
#define G1STEP(J, A) \
            acc[J][0] += A.x * w0.x + 0.f; acc[J][0] += A.y * w1.x; acc[J][0] += A.z * w2.x; acc[J][0] += A.w * w3.x; \
            acc[J][1] += A.x * w0.y;       acc[J][1] += A.y * w1.y; acc[J][1] += A.z * w2.y; acc[J][1] += A.w * w3.y; \
            acc[J][2] += A.x * w0.z;       acc[J][2] += A.y * w1.z; acc[J][2] += A.z * w2.z; acc[J][2] += A.w * w3.z; \
            acc[J][3] += A.x * w0.w;       acc[J][3] += A.y * w1.w; acc[J][3] += A.z * w2.w; acc[J][3] += A.w * w3.w;
            G1STEP(0, a0) G1STEP(1, a1) G1STEP(2, a2) G1STEP(3, a3)
#undef G1STEP
        }
    }
#pragma unroll
    for (int j = 0; j < 4; j++) {
        int gr = row0 + ty * 4 + j;
        if (gr < n) {
            float di = g_dinv[gr];
            __half2 h0 = __floats2half2_rn(acc[j][0] * di, acc[j][1] * di);
            __half2 h1 = __floats2half2_rn(acc[j][2] * di, acc[j][3] * di);
            g_hs[gr * 32 + tx * 2]     = h0;
            g_hs[gr * 32 + tx * 2 + 1] = h1;
        }
    }
}

// ---------------- gather1: g_agg = self + neighbors; fused relu epilogue -> g_zs ----------------
__global__ void k_gather1(const float* __restrict__ b1, int n) {
    int gt   = blockIdx.x * blockDim.x + threadIdx.x;
    int node = gt >> 5;
    int lane = gt & 31;
    if (node >= n) return;

    float2 acc = __half22float2(g_hs[node * 32 + lane]);   // self-loop
    int beg = g_offs[node], end = g_offs[node + 1];
    int j = beg;
    for (; j + 4 <= end; j += 4) {
        int s0 = g_csr[j], s1 = g_csr[j + 1], s2 = g_csr[j + 2], s3 = g_csr[j + 3];
        float2 v0 = __half22float2(g_hs[s0 * 32 + lane]);
        float2 v1 = __half22float2(g_hs[s1 * 32 + lane]);
        float2 v2 = __half22float2(g_hs[s2 * 32 + lane]);
        float2 v3 = __half22float2(g_hs[s3 * 32 + lane]);
        acc.x += v0.x + v1.x + v2.x + v3.x;
        acc.y += v0.y + v1.y + v2.y + v3.y;
    }
    for (; j < end; j++) {
        int s = g_csr[j];
        float2 v = __half22float2(g_hs[s * 32 + lane]);
        acc.x += v.x; acc.y += v.y;
    }
    ((float2*)g_agg)[node * 32 + lane] = acc;

    // fused relu/scale -> staging buffer g_zs (g_hs must stay intact for other warps)
    float di = g_dinv[node];
    float2 b = *(const float2*)&b1[lane * 2];
    float ox = fmaxf(acc.x * di + b.x, 0.f) * di;
    float oy = fmaxf(acc.y * di + b.y, 0.f) * di;
    g_zs[node * 32 + lane] = __floats2half2_rn(ox, oy);
}

// ---------------- gather2: g_agg2 = self + neighbors over g_zs ----------------
__global__ void k_gather2(int n) {
    int gt   = blockIdx.x * blockDim.x + threadIdx.x;
    int node = gt >> 5;
    int lane = gt & 31;
    if (node >= n) return;

    float2 acc = __half22float2(g_zs[node * 32 + lane]);   // self-loop
    int beg = g_offs[node], end = g_offs[node + 1];
    int j = beg;
    for (; j + 4 <= end; j += 4) {
        int s0 = g_csr[j], s1 = g_csr[j + 1], s2 = g_csr[j + 2], s3 = g_csr[j + 3];
        float2 v0 = __half22float2(g_zs[s0 * 32 + lane]);
        float2 v1 = __half22float2(g_zs[s1 * 32 + lane]);
        float2 v2 = __half22float2(g_zs[s2 * 32 + lane]);
        float2 v3 = __half22float2(g_zs[s3 * 32 + lane]);
        acc.x += v0.x + v1.x + v2.x + v3.x;
        acc.y += v0.y + v1.y + v2.y + v3.y;
    }
    for (; j < end; j++) {
        int s = g_csr[j];
        float2 v = __half22float2(g_zs[s * 32 + lane]);
        acc.x += v.x; acc.y += v.y;
    }
    ((float2*)g_agg2)[node * 32 + lane] = acc;
}

// ---------------- final: out = x + h1@Wl + a2@W2 + bl + b2 ----------------
// h1 = g_agg*dinv + b1 (phase 0, Wl);  a2 = g_agg2*dinv (phase 1, W2)
// 32x128 tile, 256 threads, 4x4 out/thread; k-stepped by 4 with all-float4 LDS.
__global__ void k_final(const float* __restrict__ x,  const float* __restrict__ Wl,
                        const float* __restrict__ W2, const float* __restrict__ b1,
                        const float* __restrict__ bl, const float* __restrict__ b2,
                        float* __restrict__ out, int n) {
    __shared__ __align__(16) float as[32 * 64];      // [r][k], pitch 256 B
    __shared__ __align__(16) float Ws[DHID * DOUT];  // [k][c] 32 KB
    int t = threadIdx.x;
    int row0 = blockIdx.x * 32;
    int tx = t & 31;                   // cols tx*4..+3
    int ty = t >> 5;                   // rows ty*4..+3

    float acc[4][4];
#pragma unroll
    for (int j = 0; j < 4; j++)
#pragma unroll
        for (int c = 0; c < 4; c++) acc[j][c] = 0.f;

    for (int phase = 0; phase < 2; phase++) {
        const float* A  = phase ? g_agg2 : g_agg;
        const float* Wg = phase ? W2 : Wl;
        __syncthreads();
        for (int i = t; i < 32 * DHID; i += 256) {
            int r = i >> 6, c = i & 63;
            int gr = row0 + r; if (gr >= n) gr = row0;
            float v = A[gr * DHID + c] * g_dinv[gr];
            if (phase == 0) v += b1[c];
            as[i] = v;
        }
        {
            float4* Ws4 = (float4*)Ws;
            const float4* Wg4 = (const float4*)Wg;
            for (int i = t; i < DHID * DOUT / 4; i += 256) Ws4[i] = Wg4[i];
        }
        __syncthreads();
#pragma unroll
        for (int k = 0; k < DHID; k += 4) {
            float4 a0 = *(const float4*)&as[(ty * 4 + 0) * 64 + k];
            float4 a1 = *(const float4*)&as[(ty * 4 + 1) * 64 + k];
            float4 a2 = *(const float4*)&as[(ty * 4 + 2) * 64 + k];
            float4 a3 = *(const float4*)&as[(ty * 4 + 3) * 64 + k];
            float4 w0 = *(const float4*)&Ws[(k + 0) * DOUT + tx * 4];
            float4 w1 = *(const float4*)&Ws[(k + 1) * DOUT + tx * 4];
            float4 w2 = *(const float4*)&Ws[(k + 2) * DOUT + tx * 4];
            float4 w3 = *(const float4*)&Ws[(k + 3) * DOUT + tx * 4];
#define FSTEP(J, A) \
            acc[J][0] += A.x * w0.x; acc[J][0] += A.y * w1.x; acc[J][0] += A.z * w2.x; acc[J][0] += A.w * w3.x; \
            acc[J][1] += A.x * w0.y; acc[J][1] += A.y * w1.y; acc[J][1] += A.z * w2.y; acc[J][1] += A.w * w3.y; \
            acc[J][2] += A.x * w0.z; acc[J][2] += A.y * w1.z; acc[J][2] += A.z * w2.z; acc[J][2] += A.w * w3.z; \
            acc[J][3] += A.x * w0.w; acc[J][3] += A.y * w1.w; acc[J][3] += A.z * w2.w; acc[J][3] += A.w * w3.w;
            FSTEP(0, a0) FSTEP(1, a1) FSTEP(2, a2) FSTEP(3, a3)
#undef FSTEP
        }
    }

    float4 blv = *(const float4*)&bl[tx * 4];
    float4 b2v = *(const float4*)&b2[tx * 4];
#pragma unroll
    for (int j = 0; j < 4; j++) {
        int gr = row0 + ty * 4 + j;
        if (gr < n) {
            float4 xv = *(const float4*)&x[gr * DOUT + tx * 4];
            float4 ov;
            ov.x = acc[j][0] + xv.x + blv.x + b2v.x;
            ov.y = acc[j][1] + xv.y + blv.y + b2v.y;
            ov.z = acc[j][2] + xv.z + blv.z + b2v.z;
            ov.w = acc[j][3] + xv.w + blv.w + b2v.w;
            *(float4*)&out[gr * DOUT + tx * 4] = ov;
        }
    }
}

// ---------------- launch ----------------
extern "C" void kernel_launch(void* const* d_in, const int* in_sizes, int n_in,
                              void* d_out, int out_size) {
    const float* x  = (const float*)d_in[0];
    const int*   ei = (const int*)d_in[1];          // int32 (JAX x64 disabled)
    const float* W1 = (const float*)d_in[2];
    const float* b1 = (const float*)d_in[3];
    const float* Wl = (const float*)d_in[4];
    const float* bl = (const float*)d_in[5];
    const float* W2 = (const float*)d_in[6];
    const float* b2 = (const float*)d_in[7];
    float*       out = (float*)d_out;

    int n = in_sizes[0] / DIN;        // 50000
    int e = in_sizes[1] / 2;          // 800000
    const int* src = ei;
    const int* dst = ei + e;

    int nbN = (n + 255) / 256;        // 196
    int nbE = (e + 255) / 256;        // 3125

    k_count  <<<nbE, 256>>>(dst, e);                       // 0
    k_scan1  <<<nbN, 256>>>(n);                            // 1
    k_scan2  <<<1,   256>>>(nbN);                          // 2
    k_scan3  <<<nbN, 256>>>(n, e);                         // 3  <- profiled slot
    k_gemm1  <<<(n + 63) / 64, 256>>>(x, W1, n);           // 4
    k_fill   <<<nbE, 256>>>(src, dst, e);                  // 5
    k_gather1<<<(n * 32 + 255) / 256, 256>>>(b1, n);       // 6
    k_gather2<<<(n * 32 + 255) / 256, 256>>>(n);           // 7
    k_final  <<<(n + 31) / 32, 256>>>(x, Wl, W2, b1, bl, b2, out, n);  // 8
}

// round 11
// speedup vs baseline: 2.4423x; 1.4083x over previous
#include <cuda_runtime.h>
#include <cuda_fp16.h>
#include <cstdint>

#define NN   50000
#define EE   800000
#define DIN  128
#define DHID 64
#define DOUT 128

// ---------------- scratch (static device globals; no allocation) ----------------
__device__ __align__(16) float g_dinv[NN];
__device__ int   g_cnt[NN];      // zero at load; re-zeroed by k_gemm1 each call
__device__ int   g_cur[NN];      // zero at load; re-zeroed by k_gemm1 (before k_fill)
__device__ int   g_offs[NN + 1];
__device__ int   g_csr[EE];
__device__ int   g_part[256];
__device__ int   g_part2[256];
__device__ __align__(16) __half2 g_hs[NN * 32];      // fp16 conv1 pre-agg features
__device__ __align__(16) __half2 g_zs[NN * 32];      // fp16 conv2 pre-agg features
__device__ __align__(16) float   g_agg [NN * DHID];  // gather1 result (fp32)
__device__ __align__(16) float   g_agg2[NN * DHID];  // gather2 result (fp32)

__device__ __forceinline__ uint32_t smem_u32(const void* p) {
    return (uint32_t)__cvta_generic_to_shared(p);
}

#define LDMATRIX_X4(a0,a1,a2,a3,addr) \
    asm volatile("ldmatrix.sync.aligned.m8n8.x4.shared.b16 {%0,%1,%2,%3}, [%4];" \
        : "=r"(a0),"=r"(a1),"=r"(a2),"=r"(a3) : "r"(addr))
#define LDMATRIX_X2T(b0,b1,addr) \
    asm volatile("ldmatrix.sync.aligned.m8n8.x2.trans.shared.b16 {%0,%1}, [%2];" \
        : "=r"(b0),"=r"(b1) : "r"(addr))
#define MMA16816(d0,d1,d2,d3,a0,a1,a2,a3,b0,b1) \
    asm volatile("mma.sync.aligned.m16n8k16.row.col.f32.f16.f16.f32 " \
        "{%0,%1,%2,%3},{%4,%5,%6,%7},{%8,%9},{%0,%1,%2,%3};" \
        : "+f"(d0),"+f"(d1),"+f"(d2),"+f"(d3) \
        : "r"(a0),"r"(a1),"r"(a2),"r"(a3),"r"(b0),"r"(b1))

// ---------------- CSR build ----------------
__global__ void k_count(const int* __restrict__ dst, int e) {
    int i = blockIdx.x * blockDim.x + threadIdx.x;
    if (i < e) atomicAdd(&g_cnt[dst[i]], 1);
}

__global__ void k_dinv(int n) {
    int i = blockIdx.x * blockDim.x + threadIdx.x;
    if (i < n) g_dinv[i] = rsqrtf((float)g_cnt[i] + 1.0f);
}

__global__ void k_scan1(int n) {
    __shared__ int sh[256];
    int t = threadIdx.x;
    int i = blockIdx.x * 256 + t;
    int v = (i < n) ? g_cnt[i] : 0;
    sh[t] = v;
    for (int off = 1; off < 256; off <<= 1) {
        __syncthreads();
        int x = (t >= off) ? sh[t - off] : 0;
        __syncthreads();
        sh[t] += x;
    }
    __syncthreads();
    if (i < n) g_offs[i] = sh[t] - v;
    if (t == 255) g_part[blockIdx.x] = sh[255];
}

__global__ void k_scan2(int nb) {
    __shared__ int sh[256];
    int t = threadIdx.x;
    int v = (t < nb) ? g_part[t] : 0;
    sh[t] = v;
    for (int off = 1; off < 256; off <<= 1) {
        __syncthreads();
        int x = (t >= off) ? sh[t - off] : 0;
        __syncthreads();
        sh[t] += x;
    }
    __syncthreads();
    g_part2[t] = sh[t] - v;
}

__global__ void k_scan3(int n, int e) {
    int i = blockIdx.x * 256 + threadIdx.x;
    if (i < n) g_offs[i] += g_part2[blockIdx.x];
    if (i == 0) g_offs[n] = e;
}

__global__ void k_fill(const int* __restrict__ src,
                       const int* __restrict__ dst, int e) {
    int i = blockIdx.x * blockDim.x + threadIdx.x;
    if (i < e) {
        int d = dst[i];
        int p = g_offs[d] + atomicAdd(&g_cur[d], 1);
        g_csr[p] = src[i];
    }
}

// ---------------- GEMM1 (HMMA): g_hs = fp16( (x @ W1) * dinv[row] ) ----------------
// 64-row tile, 256 thr = 8 warps (4m x 2n), warp tile 16x32, K=128 in 8 mma-k steps.
// Also re-zeroes g_cnt/g_cur (consumed by next replay's k_count, and this call's k_fill).
__global__ void k_gemm1(const float* __restrict__ x, const float* __restrict__ W1, int n) {
    __shared__ __align__(16) __half As[64 * 136];   // [row][k] pitch 136 halves (272 B)
    __shared__ __align__(16) __half Bs[128 * 72];   // [k][c]  pitch 72 halves (144 B)
    int t = threadIdx.x;
    int lane = t & 31, w = t >> 5;
    int wm = w & 3, wn = w >> 2;
    int row0 = blockIdx.x * 64;

    for (int i = blockIdx.x * 256 + t; i < n; i += gridDim.x * 256) {
        g_cnt[i] = 0; g_cur[i] = 0;
    }

    // x[64][128] fp32 -> fp16 As
    for (int i = t; i < 64 * 32; i += 256) {
        int r = i >> 5, c4 = i & 31;
        int gr = row0 + r; if (gr >= n) gr = row0;
        float4 v = *(const float4*)&x[gr * DIN + c4 * 4];
        *(__half2*)&As[r * 136 + c4 * 4]     = __floats2half2_rn(v.x, v.y);
        *(__half2*)&As[r * 136 + c4 * 4 + 2] = __floats2half2_rn(v.z, v.w);
    }
    // W1[128][64] fp32 -> fp16 Bs
    for (int i = t; i < 128 * 16; i += 256) {
        int k = i >> 4, c4 = i & 15;
        float4 v = *(const float4*)&W1[k * DHID + c4 * 4];
        *(__half2*)&Bs[k * 72 + c4 * 4]     = __floats2half2_rn(v.x, v.y);
        *(__half2*)&Bs[k * 72 + c4 * 4 + 2] = __floats2half2_rn(v.z, v.w);
    }
    __syncthreads();

    float d[2][4][4];   // [unused=1 layer kept small] -> use [4 nf][4 regs]
    float acc[4][4];
#pragma unroll
    for (int nf = 0; nf < 4; nf++)
#pragma unroll
        for (int r = 0; r < 4; r++) acc[nf][r] = 0.f;
    (void)d;

    int arow = wm * 16 + (lane & 15);
    int acol8 = (lane >> 4) * 8;
#pragma unroll
    for (int ks = 0; ks < 8; ks++) {
        int k0 = ks * 16;
        uint32_t a0, a1, a2, a3;
        LDMATRIX_X4(a0, a1, a2, a3, smem_u32(&As[arow * 136 + k0 + acol8]));
#pragma unroll
        for (int nf = 0; nf < 4; nf++) {
            uint32_t b0, b1;
            LDMATRIX_X2T(b0, b1, smem_u32(&Bs[(k0 + (lane & 15)) * 72 + wn * 32 + nf * 8]));
            MMA16816(acc[nf][0], acc[nf][1], acc[nf][2], acc[nf][3], a0, a1, a2, a3, b0, b1);
        }
    }

    int g = lane >> 2, tig = lane & 3;
#pragma unroll
    for (int half = 0; half < 2; half++) {
        int gr = row0 + wm * 16 + g + half * 8;
        if (gr < n) {
            float di = g_dinv[gr];
#pragma unroll
            for (int nf = 0; nf < 4; nf++) {
                float c0 = acc[nf][half * 2] * di;
                float c1 = acc[nf][half * 2 + 1] * di;
                g_hs[gr * 32 + wn * 16 + nf * 4 + tig] = __floats2half2_rn(c0, c1);
            }
        }
    }
}

// ---------------- gather1: g_agg = self + neighbors; fused relu epilogue -> g_zs ----------------
__global__ void k_gather1(const float* __restrict__ b1, int n) {
    int gt   = blockIdx.x * blockDim.x + threadIdx.x;
    int node = gt >> 5;
    int lane = gt & 31;
    if (node >= n) return;

    float2 acc = __half22float2(g_hs[node * 32 + lane]);
    int beg = g_offs[node], end = g_offs[node + 1];
    int j = beg;
    for (; j + 4 <= end; j += 4) {
        int s0 = g_csr[j], s1 = g_csr[j + 1], s2 = g_csr[j + 2], s3 = g_csr[j + 3];
        float2 v0 = __half22float2(g_hs[s0 * 32 + lane]);
        float2 v1 = __half22float2(g_hs[s1 * 32 + lane]);
        float2 v2 = __half22float2(g_hs[s2 * 32 + lane]);
        float2 v3 = __half22float2(g_hs[s3 * 32 + lane]);
        acc.x += v0.x + v1.x + v2.x + v3.x;
        acc.y += v0.y + v1.y + v2.y + v3.y;
    }
    for (; j < end; j++) {
        int s = g_csr[j];
        float2 v = __half22float2(g_hs[s * 32 + lane]);
        acc.x += v.x; acc.y += v.y;
    }
    ((float2*)g_agg)[node * 32 + lane] = acc;

    float di = g_dinv[node];
    float2 b = *(const float2*)&b1[lane * 2];
    float ox = fmaxf(acc.x * di + b.x, 0.f) * di;
    float oy = fmaxf(acc.y * di + b.y, 0.f) * di;
    g_zs[node * 32 + lane] = __floats2half2_rn(ox, oy);
}

// ---------------- gather2: g_agg2 = self + neighbors over g_zs ----------------
__global__ void k_gather2(int n) {
    int gt   = blockIdx.x * blockDim.x + threadIdx.x;
    int node = gt >> 5;
    int lane = gt & 31;
    if (node >= n) return;

    float2 acc = __half22float2(g_zs[node * 32 + lane]);
    int beg = g_offs[node], end = g_offs[node + 1];
    int j = beg;
    for (; j + 4 <= end; j += 4) {
        int s0 = g_csr[j], s1 = g_csr[j + 1], s2 = g_csr[j + 2], s3 = g_csr[j + 3];
        float2 v0 = __half22float2(g_zs[s0 * 32 + lane]);
        float2 v1 = __half22float2(g_zs[s1 * 32 + lane]);
        float2 v2 = __half22float2(g_zs[s2 * 32 + lane]);
        float2 v3 = __half22float2(g_zs[s3 * 32 + lane]);
        acc.x += v0.x + v1.x + v2.x + v3.x;
        acc.y += v0.y + v1.y + v2.y + v3.y;
    }
    for (; j < end; j++) {
        int s = g_csr[j];
        float2 v = __half22float2(g_zs[s * 32 + lane]);
        acc.x += v.x; acc.y += v.y;
    }
    ((float2*)g_agg2)[node * 32 + lane] = acc;
}

// ---------------- final (HMMA): out = x + h1@Wl + a2@W2 + bl + b2 ----------------
// 32-row tile, 256 thr = 8 warps (2m x 4n), warp tile 16x32; two K=64 phases accumulate.
__global__ void k_final(const float* __restrict__ x,  const float* __restrict__ Wl,
                        const float* __restrict__ W2, const float* __restrict__ b1,
                        const float* __restrict__ bl, const float* __restrict__ b2,
                        float* __restrict__ out, int n) {
    __shared__ __align__(16) __half As[32 * 72];     // [row][k] pitch 72 halves
    __shared__ __align__(16) __half Bs[64 * 136];    // [k][c]  pitch 136 halves
    int t = threadIdx.x;
    int lane = t & 31, w = t >> 5;
    int wm = w & 1, wn = w >> 1;
    int row0 = blockIdx.x * 32;

    float acc[4][4];
#pragma unroll
    for (int nf = 0; nf < 4; nf++)
#pragma unroll
        for (int r = 0; r < 4; r++) acc[nf][r] = 0.f;

    for (int phase = 0; phase < 2; phase++) {
        const float* A  = phase ? g_agg2 : g_agg;
        const float* Wg = phase ? W2 : Wl;
        __syncthreads();
        // A tile: (agg*dinv [+ b1]) -> fp16
        for (int i = t; i < 32 * 16; i += 256) {
            int r = i >> 4, c4 = i & 15;
            int gr = row0 + r; if (gr >= n) gr = row0;
            float di = g_dinv[gr];
            float4 v = *(const float4*)&A[gr * DHID + c4 * 4];
            v.x *= di; v.y *= di; v.z *= di; v.w *= di;
            if (phase == 0) {
                float4 b = *(const float4*)&b1[c4 * 4];
                v.x += b.x; v.y += b.y; v.z += b.z; v.w += b.w;
            }
            *(__half2*)&As[r * 72 + c4 * 4]     = __floats2half2_rn(v.x, v.y);
            *(__half2*)&As[r * 72 + c4 * 4 + 2] = __floats2half2_rn(v.z, v.w);
        }
        // B tile: W[64][128] fp32 -> fp16
        for (int i = t; i < 64 * 32; i += 256) {
            int k = i >> 5, c4 = i & 31;
            float4 v = *(const float4*)&Wg[k * DOUT + c4 * 4];
            *(__half2*)&Bs[k * 136 + c4 * 4]     = __floats2half2_rn(v.x, v.y);
            *(__half2*)&Bs[k * 136 + c4 * 4 + 2] = __floats2half2_rn(v.z, v.w);
        }
        __syncthreads();

        int arow = wm * 16 + (lane & 15);
        int acol8 = (lane >> 4) * 8;
#pragma unroll
        for (int ks = 0; ks < 4; ks++) {
            int k0 = ks * 16;
            uint32_t a0, a1, a2, a3;
            LDMATRIX_X4(a0, a1, a2, a3, smem_u32(&As[arow * 72 + k0 + acol8]));
#pragma unroll
            for (int nf = 0; nf < 4; nf++) {
                uint32_t b0, b1r;
                LDMATRIX_X2T(b0, b1r, smem_u32(&Bs[(k0 + (lane & 15)) * 136 + wn * 32 + nf * 8]));
                MMA16816(acc[nf][0], acc[nf][1], acc[nf][2], acc[nf][3], a0, a1, a2, a3, b0, b1r);
            }
        }
    }

    int g = lane >> 2, tig = lane & 3;
#pragma unroll
    for (int half = 0; half < 2; half++) {
        int gr = row0 + wm * 16 + g + half * 8;
        if (gr < n) {
#pragma unroll
            for (int nf = 0; nf < 4; nf++) {
                int nc = wn * 32 + nf * 8 + tig * 2;
                float2 xv  = *(const float2*)&x[gr * DOUT + nc];
                float2 blv = *(const float2*)&bl[nc];
                float2 b2v = *(const float2*)&b2[nc];
                float2 ov;
                ov.x = acc[nf][half * 2]     + xv.x + blv.x + b2v.x;
                ov.y = acc[nf][half * 2 + 1] + xv.y + blv.y + b2v.y;
                *(float2*)&out[gr * DOUT + nc] = ov;
            }
        }
    }
}

// ---------------- launch ----------------
// Order: gemm1 in ncu slot 3. Note gemm1 zeroes g_cnt, so it must come AFTER
// k_dinv and k_scan1 (the g_cnt readers) — and it does.
extern "C" void kernel_launch(void* const* d_in, const int* in_sizes, int n_in,
                              void* d_out, int out_size) {
    const float* x  = (const float*)d_in[0];
    const int*   ei = (const int*)d_in[1];          // int32 (JAX x64 disabled)
    const float* W1 = (const float*)d_in[2];
    const float* b1 = (const float*)d_in[3];
    const float* Wl = (const float*)d_in[4];
    const float* bl = (const float*)d_in[5];
    const float* W2 = (const float*)d_in[6];
    const float* b2 = (const float*)d_in[7];
    float*       out = (float*)d_out;

    int n = in_sizes[0] / DIN;        // 50000
    int e = in_sizes[1] / 2;          // 800000
    const int* src = ei;
    const int* dst = ei + e;

    int nbN = (n + 255) / 256;        // 196
    int nbE = (e + 255) / 256;        // 3125

    k_count  <<<nbE, 256>>>(dst, e);                       // 0
    k_dinv   <<<nbN, 256>>>(n);                            // 1
    k_scan1  <<<nbN, 256>>>(n);                            // 2
    k_gemm1  <<<(n + 63) / 64, 256>>>(x, W1, n);           // 3  <- profiled slot
    k_scan2  <<<1,   256>>>(nbN);                          // 4
    k_scan3  <<<nbN, 256>>>(n, e);                         // 5
    k_fill   <<<nbE, 256>>>(src, dst, e);                  // 6
    k_gather1<<<(n * 32 + 255) / 256, 256>>>(b1, n);       // 7
    k_gather2<<<(n * 32 + 255) / 256, 256>>>(n);           // 8
    k_final  <<<(n + 31) / 32, 256>>>(x, Wl, W2, b1, bl, b2, out, n);  // 9
}

// round 12
// speedup vs baseline: 2.4898x; 1.0194x over previous
#include <cuda_runtime.h>
#include <cuda_fp16.h>
#include <cstdint>

#define NN   50000
#define EE   800000
#define DIN  128
#define DHID 64
#define DOUT 128

// ---------------- scratch (static device globals; no allocation) ----------------
__device__ __align__(16) float g_dinv[NN];
__device__ int   g_cnt[NN];      // zero at load; re-zeroed by fused gemm blocks each call
__device__ int   g_rank[EE];     // per-edge rank within its dst bucket (from k_count)
__device__ int   g_offs[NN];     // block-local exclusive prefix (scan1)
__device__ int   g_part[256];
__device__ int   g_part2[256];   // per-256-block global offset (scan2)
__device__ int   g_csr[EE];
__device__ __align__(16) __half2 g_hs[NN * 32];      // fp16 conv1 pre-agg features
__device__ __align__(16) __half2 g_zs[NN * 32];      // fp16 conv2 pre-agg features
__device__ __align__(16) float   g_agg [NN * DHID];  // gather1 result (fp32)
__device__ __align__(16) float   g_agg2[NN * DHID];  // gather2 result (fp32)

__device__ __forceinline__ uint32_t smem_u32(const void* p) {
    return (uint32_t)__cvta_generic_to_shared(p);
}

#define LDMATRIX_X4(a0,a1,a2,a3,addr) \
    asm volatile("ldmatrix.sync.aligned.m8n8.x4.shared.b16 {%0,%1,%2,%3}, [%4];" \
        : "=r"(a0),"=r"(a1),"=r"(a2),"=r"(a3) : "r"(addr))
#define LDMATRIX_X2T(b0,b1,addr) \
    asm volatile("ldmatrix.sync.aligned.m8n8.x2.trans.shared.b16 {%0,%1}, [%2];" \
        : "=r"(b0),"=r"(b1) : "r"(addr))
#define MMA16816(d0,d1,d2,d3,a0,a1,a2,a3,b0,b1) \
    asm volatile("mma.sync.aligned.m16n8k16.row.col.f32.f16.f16.f32 " \
        "{%0,%1,%2,%3},{%4,%5,%6,%7},{%8,%9},{%0,%1,%2,%3};" \
        : "+f"(d0),"+f"(d1),"+f"(d2),"+f"(d3) \
        : "r"(a0),"r"(a1),"r"(a2),"r"(a3),"r"(b0),"r"(b1))

// ---------------- count: degree histogram + per-edge rank ----------------
__global__ void k_count(const int* __restrict__ dst, int e) {
    int i = blockIdx.x * blockDim.x + threadIdx.x;
    if (i < e) g_rank[i] = atomicAdd(&g_cnt[dst[i]], 1);
}

// ---------------- scan1: block-local exclusive prefix of counts; + dinv ----------------
__global__ void k_scan1(int n) {
    __shared__ int sh[256];
    int t = threadIdx.x;
    int i = blockIdx.x * 256 + t;
    int v = (i < n) ? g_cnt[i] : 0;
    sh[t] = v;
    for (int off = 1; off < 256; off <<= 1) {
        __syncthreads();
        int x = (t >= off) ? sh[t - off] : 0;
        __syncthreads();
        sh[t] += x;
    }
    __syncthreads();
    if (i < n) {
        g_offs[i] = sh[t] - v;
        g_dinv[i] = rsqrtf((float)v + 1.0f);
    }
    if (t == 255) g_part[blockIdx.x] = sh[255];
}

// ---------------- scan2: exclusive prefix of block sums ----------------
__global__ void k_scan2(int nb) {
    __shared__ int sh[256];
    int t = threadIdx.x;
    int v = (t < nb) ? g_part[t] : 0;
    sh[t] = v;
    for (int off = 1; off < 256; off <<= 1) {
        __syncthreads();
        int x = (t >= off) ? sh[t - off] : 0;
        __syncthreads();
        sh[t] += x;
    }
    __syncthreads();
    g_part2[t] = sh[t] - v;
}

// ---------------- fused: CSR fill (blocks < nbE) + GEMM1 HMMA (rest) ----------------
// fill: csr[offs(d)+rank[i]] = src[i] — no atomics (rank precomputed).
// gemm: g_hs = fp16((x@W1)*dinv[row]); also zeroes g_cnt for the next replay.
__global__ void k_big(const int* __restrict__ src, const int* __restrict__ dst, int e,
                      const float* __restrict__ x, const float* __restrict__ W1,
                      int n, int nbE) {
    __shared__ __align__(16) __half As[64 * 136];   // [row][k] pitch 136 halves
    __shared__ __align__(16) __half Bs[128 * 72];   // [k][c]  pitch 72 halves
    int t = threadIdx.x;

    if (blockIdx.x < nbE) {
        int i = blockIdx.x * 256 + t;
        if (i < e) {
            int d = dst[i];
            int p = g_offs[d] + g_part2[d >> 8] + g_rank[i];
            g_csr[p] = src[i];
        }
        return;
    }

    int gb = blockIdx.x - nbE;
    int row0 = gb * 64;
    int lane = t & 31, w = t >> 5;
    int wm = w & 3, wn = w >> 2;

    // zero g_cnt for next replay (scan1 has already consumed it)
    int ngb = gridDim.x - nbE;
    for (int i = gb * 256 + t; i < n; i += ngb * 256) g_cnt[i] = 0;

    // x[64][128] fp32 -> fp16 As
    for (int i = t; i < 64 * 32; i += 256) {
        int r = i >> 5, c4 = i & 31;
        int gr = row0 + r; if (gr >= n) gr = row0;
        float4 v = *(const float4*)&x[gr * DIN + c4 * 4];
        *(__half2*)&As[r * 136 + c4 * 4]     = __floats2half2_rn(v.x, v.y);
        *(__half2*)&As[r * 136 + c4 * 4 + 2] = __floats2half2_rn(v.z, v.w);
    }
    // W1[128][64] fp32 -> fp16 Bs
    for (int i = t; i < 128 * 16; i += 256) {
        int k = i >> 4, c4 = i & 15;
        float4 v = *(const float4*)&W1[k * DHID + c4 * 4];
        *(__half2*)&Bs[k * 72 + c4 * 4]     = __floats2half2_rn(v.x, v.y);
        *(__half2*)&Bs[k * 72 + c4 * 4 + 2] = __floats2half2_rn(v.z, v.w);
    }
    __syncthreads();

    float acc[4][4];
#pragma unroll
    for (int nf = 0; nf < 4; nf++)
#pragma unroll
        for (int r = 0; r < 4; r++) acc[nf][r] = 0.f;

    int arow = wm * 16 + (lane & 15);
    int acol8 = (lane >> 4) * 8;
#pragma unroll
    for (int ks = 0; ks < 8; ks++) {
        int k0 = ks * 16;
        uint32_t a0, a1, a2, a3;
        LDMATRIX_X4(a0, a1, a2, a3, smem_u32(&As[arow * 136 + k0 + acol8]));
#pragma unroll
        for (int nf = 0; nf < 4; nf++) {
            uint32_t b0, b1;
            LDMATRIX_X2T(b0, b1, smem_u32(&Bs[(k0 + (lane & 15)) * 72 + wn * 32 + nf * 8]));
            MMA16816(acc[nf][0], acc[nf][1], acc[nf][2], acc[nf][3], a0, a1, a2, a3, b0, b1);
        }
    }

    int g = lane >> 2, tig = lane & 3;
#pragma unroll
    for (int half = 0; half < 2; half++) {
        int gr = row0 + wm * 16 + g + half * 8;
        if (gr < n) {
            float di = g_dinv[gr];
#pragma unroll
            for (int nf = 0; nf < 4; nf++) {
                float c0 = acc[nf][half * 2] * di;
                float c1 = acc[nf][half * 2 + 1] * di;
                g_hs[gr * 32 + wn * 16 + nf * 4 + tig] = __floats2half2_rn(c0, c1);
            }
        }
    }
}

// final offsets: offs(v) = g_offs[v] + g_part2[v>>8];  end-of-last = e
__device__ __forceinline__ int offs_beg(int v)        { return g_offs[v] + g_part2[v >> 8]; }
__device__ __forceinline__ int offs_end(int v, int n, int e) {
    return (v + 1 < n) ? g_offs[v + 1] + g_part2[(v + 1) >> 8] : e;
}

// ---------------- gather1: g_agg = self + neighbors; fused relu epilogue -> g_zs ----------------
__global__ void k_gather1(const float* __restrict__ b1, int n, int e) {
    int gt   = blockIdx.x * blockDim.x + threadIdx.x;
    int node = gt >> 5;
    int lane = gt & 31;
    if (node >= n) return;

    float2 acc = __half22float2(g_hs[node * 32 + lane]);
    int beg = offs_beg(node), end = offs_end(node, n, e);
    int j = beg;
    for (; j + 4 <= end; j += 4) {
        int s0 = g_csr[j], s1 = g_csr[j + 1], s2 = g_csr[j + 2], s3 = g_csr[j + 3];
        float2 v0 = __half22float2(g_hs[s0 * 32 + lane]);
        float2 v1 = __half22float2(g_hs[s1 * 32 + lane]);
        float2 v2 = __half22float2(g_hs[s2 * 32 + lane]);
        float2 v3 = __half22float2(g_hs[s3 * 32 + lane]);
        acc.x += v0.x + v1.x + v2.x + v3.x;
        acc.y += v0.y + v1.y + v2.y + v3.y;
    }
    for (; j < end; j++) {
        int s = g_csr[j];
        float2 v = __half22float2(g_hs[s * 32 + lane]);
        acc.x += v.x; acc.y += v.y;
    }
    ((float2*)g_agg)[node * 32 + lane] = acc;

    float di = g_dinv[node];
    float2 b = *(const float2*)&b1[lane * 2];
    float ox = fmaxf(acc.x * di + b.x, 0.f) * di;
    float oy = fmaxf(acc.y * di + b.y, 0.f) * di;
    g_zs[node * 32 + lane] = __floats2half2_rn(ox, oy);
}

// ---------------- gather2: g_agg2 = self + neighbors over g_zs ----------------
__global__ void k_gather2(int n, int e) {
    int gt   = blockIdx.x * blockDim.x + threadIdx.x;
    int node = gt >> 5;
    int lane = gt & 31;
    if (node >= n) return;

    float2 acc = __half22float2(g_zs[node * 32 + lane]);
    int beg = offs_beg(node), end = offs_end(node, n, e);
    int j = beg;
    for (; j + 4 <= end; j += 4) {
        int s0 = g_csr[j], s1 = g_csr[j + 1], s2 = g_csr[j + 2], s3 = g_csr[j + 3];
        float2 v0 = __half22float2(g_zs[s0 * 32 + lane]);
        float2 v1 = __half22float2(g_zs[s1 * 32 + lane]);
        float2 v2 = __half22float2(g_zs[s2 * 32 + lane]);
        float2 v3 = __half22float2(g_zs[s3 * 32 + lane]);
        acc.x += v0.x + v1.x + v2.x + v3.x;
        acc.y += v0.y + v1.y + v2.y + v3.y;
    }
    for (; j < end; j++) {
        int s = g_csr[j];
        float2 v = __half22float2(g_zs[s * 32 + lane]);
        acc.x += v.x; acc.y += v.y;
    }
    ((float2*)g_agg2)[node * 32 + lane] = acc;
}

// ---------------- final (HMMA): out = x + h1@Wl + a2@W2 + bl + b2 ----------------
__global__ void k_final(const float* __restrict__ x,  const float* __restrict__ Wl,
                        const float* __restrict__ W2, const float* __restrict__ b1,
                        const float* __restrict__ bl, const float* __restrict__ b2,
                        float* __restrict__ out, int n) {
    __shared__ __align__(16) __half As[32 * 72];     // [row][k] pitch 72 halves
    __shared__ __align__(16) __half Bs[64 * 136];    // [k][c]  pitch 136 halves
    int t = threadIdx.x;
    int lane = t & 31, w = t >> 5;
    int wm = w & 1, wn = w >> 1;
    int row0 = blockIdx.x * 32;

    float acc[4][4];
#pragma unroll
    for (int nf = 0; nf < 4; nf++)
#pragma unroll
        for (int r = 0; r < 4; r++) acc[nf][r] = 0.f;

    for (int phase = 0; phase < 2; phase++) {
        const float* A  = phase ? g_agg2 : g_agg;
        const float* Wg = phase ? W2 : Wl;
        __syncthreads();
        for (int i = t; i < 32 * 16; i += 256) {
            int r = i >> 4, c4 = i & 15;
            int gr = row0 + r; if (gr >= n) gr = row0;
            float di = g_dinv[gr];
            float4 v = *(const float4*)&A[gr * DHID + c4 * 4];
            v.x *= di; v.y *= di; v.z *= di; v.w *= di;
            if (phase == 0) {
                float4 b = *(const float4*)&b1[c4 * 4];
                v.x += b.x; v.y += b.y; v.z += b.z; v.w += b.w;
            }
            *(__half2*)&As[r * 72 + c4 * 4]     = __floats2half2_rn(v.x, v.y);
            *(__half2*)&As[r * 72 + c4 * 4 + 2] = __floats2half2_rn(v.z, v.w);
        }
        for (int i = t; i < 64 * 32; i += 256) {
            int k = i >> 5, c4 = i & 31;
            float4 v = *(const float4*)&Wg[k * DOUT + c4 * 4];
            *(__half2*)&Bs[k * 136 + c4 * 4]     = __floats2half2_rn(v.x, v.y);
            *(__half2*)&Bs[k * 136 + c4 * 4 + 2] = __floats2half2_rn(v.z, v.w);
        }
        __syncthreads();

        int arow = wm * 16 + (lane & 15);
        int acol8 = (lane >> 4) * 8;
#pragma unroll
        for (int ks = 0; ks < 4; ks++) {
            int k0 = ks * 16;
            uint32_t a0, a1, a2, a3;
            LDMATRIX_X4(a0, a1, a2, a3, smem_u32(&As[arow * 72 + k0 + acol8]));
#pragma unroll
            for (int nf = 0; nf < 4; nf++) {
                uint32_t b0, b1r;
                LDMATRIX_X2T(b0, b1r, smem_u32(&Bs[(k0 + (lane & 15)) * 136 + wn * 32 + nf * 8]));
                MMA16816(acc[nf][0], acc[nf][1], acc[nf][2], acc[nf][3], a0, a1, a2, a3, b0, b1r);
            }
        }
    }

    int g = lane >> 2, tig = lane & 3;
#pragma unroll
    for (int half = 0; half < 2; half++) {
        int gr = row0 + wm * 16 + g + half * 8;
        if (gr < n) {
#pragma unroll
            for (int nf = 0; nf < 4; nf++) {
                int nc = wn * 32 + nf * 8 + tig * 2;
                float2 xv  = *(const float2*)&x[gr * DOUT + nc];
                float2 blv = *(const float2*)&bl[nc];
                float2 b2v = *(const float2*)&b2[nc];
                float2 ov;
                ov.x = acc[nf][half * 2]     + xv.x + blv.x + b2v.x;
                ov.y = acc[nf][half * 2 + 1] + xv.y + blv.y + b2v.y;
                *(float2*)&out[gr * DOUT + nc] = ov;
            }
        }
    }
}

// ---------------- launch (7 kernels; slot 3 = fused gemm+fill) ----------------
extern "C" void kernel_launch(void* const* d_in, const int* in_sizes, int n_in,
                              void* d_out, int out_size) {
    const float* x  = (const float*)d_in[0];
    const int*   ei = (const int*)d_in[1];          // int32 (JAX x64 disabled)
    const float* W1 = (const float*)d_in[2];
    const float* b1 = (const float*)d_in[3];
    const float* Wl = (const float*)d_in[4];
    const float* bl = (const float*)d_in[5];
    const float* W2 = (const float*)d_in[6];
    const float* b2 = (const float*)d_in[7];
    float*       out = (float*)d_out;

    int n = in_sizes[0] / DIN;        // 50000
    int e = in_sizes[1] / 2;          // 800000
    const int* src = ei;
    const int* dst = ei + e;

    int nbN = (n + 255) / 256;        // 196
    int nbE = (e + 255) / 256;        // 3125
    int nbG = (n + 63) / 64;          // 782

    k_count  <<<nbE, 256>>>(dst, e);                        // 0
    k_scan1  <<<nbN, 256>>>(n);                             // 1 (+dinv)
    k_scan2  <<<1,   256>>>(nbN);                           // 2
    k_big    <<<nbE + nbG, 256>>>(src, dst, e, x, W1, n, nbE); // 3 <- profiled
    k_gather1<<<(n * 32 + 255) / 256, 256>>>(b1, n, e);     // 4
    k_gather2<<<(n * 32 + 255) / 256, 256>>>(n, e);         // 5
    k_final  <<<(n + 31) / 32, 256>>>(x, Wl, W2, b1, bl, b2, out, n);  // 6
}